// round 9
// baseline (speedup 1.0000x reference)
#include <cuda_runtime.h>
#include <cuda_fp16.h>
#include <mma.h>
#include <math_constants.h>
#include <cstdint>

using namespace nvcuda;

#define S_LEN 4096
#define DIM   2048
#define HEADS 16
#define HD    128
#define GK    2048
#define BM    128
#define BN    128
#define BKC   64
#define NKC   (GK / BKC)    // 32
#define SLD   80            // int8 gemm smem row stride
#define FSLD  72            // fp16 gemm smem row stride

// int8 fixed-point scales
#define SACT   5400.0f
#define SWGT   240000.0f
#define SCALE_OUT (1.0f / (SACT * SWGT))
#define SLOGIT (0.08838834764831843f / (SACT * SACT))
#define PSCALE 30000.0f

// ---------------- scratch (allocation-free rule: __device__ globals) ----------
__device__ signed char g_Qhi[HEADS * S_LEN * HD];
__device__ signed char g_Qlo[HEADS * S_LEN * HD];
__device__ signed char g_Khi[HEADS * S_LEN * HD];
__device__ signed char g_Klo[HEADS * S_LEN * HD];
__device__ signed char g_Vhi[HEADS * S_LEN * HD];
__device__ signed char g_Vlo[HEADS * S_LEN * HD];
__device__ signed char g_Xhi[S_LEN * DIM];
__device__ signed char g_Xlo[S_LEN * DIM];
__device__ signed char g_Whi[3][DIM * DIM];
__device__ signed char g_Wlo[3][DIM * DIM];
__device__ __half      g_Ohi[S_LEN * DIM];
__device__ __half      g_Olo[S_LEN * DIM];
__device__ __half      g_Wo16[DIM * DIM];

// ---------------- helpers ------------------------------------------------------
__device__ __forceinline__ uint32_t smem_u32(const void* p) {
    uint32_t a;
    asm("{ .reg .u64 t; cvta.to.shared.u64 t, %1; cvt.u32.u64 %0, t; }"
        : "=r"(a) : "l"(p));
    return a;
}
#define CP_ASYNC16(dst_u32, src_ptr) \
    asm volatile("cp.async.cg.shared.global [%0], [%1], 16;" \
        :: "r"(dst_u32), "l"(src_ptr) : "memory")
#define CP_ASYNC_COMMIT() asm volatile("cp.async.commit_group;" ::: "memory")
#define CP_ASYNC_WAIT0()  asm volatile("cp.async.wait_group 0;" ::: "memory")
#define CP_ASYNC_WAIT1()  asm volatile("cp.async.wait_group 1;" ::: "memory")

__device__ __forceinline__ void qsplit(float x, float s, int& qh, int& ql) {
    int q = __float2int_rn(x * s);
    q = max(-32639, min(32639, q));
    ql = (int)((unsigned)(q + 128) & 255u) - 128;
    qh = (q - ql) >> 8;
}
__device__ __forceinline__ uint32_t pack4(int b0, int b1, int b2, int b3) {
    return (uint32_t)(b0 & 255) | ((uint32_t)(b1 & 255) << 8) |
           ((uint32_t)(b2 & 255) << 16) | ((uint32_t)(b3 & 255) << 24);
}
__device__ __forceinline__ uint32_t pack_h2(__half a, __half b) {
    __half2 t = __halves2half2(a, b);
    return *(uint32_t*)&t;
}

// ============================================================================
// splits
// ============================================================================
__global__ void split8(const float4* __restrict__ src,
                       uint32_t* __restrict__ hi, uint32_t* __restrict__ lo,
                       int n4, float s) {
    int i = blockIdx.x * 256 + threadIdx.x;
    if (i >= n4) return;
    float4 v = src[i];
    int h0, l0, h1, l1, h2, l2, h3, l3;
    qsplit(v.x, s, h0, l0);
    qsplit(v.y, s, h1, l1);
    qsplit(v.z, s, h2, l2);
    qsplit(v.w, s, h3, l3);
    hi[i] = pack4(h0, h1, h2, h3);
    lo[i] = pack4(l0, l1, l2, l3);
}

__global__ void split_h16(const float4* __restrict__ src,
                          uint2* __restrict__ hi, int n4) {
    int i = blockIdx.x * 256 + threadIdx.x;
    if (i >= n4) return;
    float4 v = src[i];
    uint2 ho;
    ho.x = pack_h2(__float2half(v.x), __float2half(v.y));
    ho.y = pack_h2(__float2half(v.z), __float2half(v.w));
    hi[i] = ho;
}

// ============================================================================
// IMMA GEMM (QKV projections): C = A*B^T + bias, re-quantized int8 hi/lo out,
// head layout [N/128][M][128].
// ============================================================================
#define TILE_BYTES (128 * SLD)
#define BUF_BYTES  (4 * TILE_BYTES)
#define GEMM_SMEM  (2 * BUF_BYTES)             // 81920

__global__ __launch_bounds__(256, 1) void gemm_imma(
    const signed char* __restrict__ Ahi, const signed char* __restrict__ Alo,
    const signed char* __restrict__ Bhi, const signed char* __restrict__ Blo,
    const float* __restrict__ bias,
    signed char* __restrict__ Chi, signed char* __restrict__ Clo,
    int M, int N)
{
    extern __shared__ char smemg[];
    signed char* sbuf = (signed char*)smemg;
    const uint32_t sb = smem_u32(smemg);

    const int tid  = threadIdx.x;
    const int wid  = tid >> 5;
    const int m0   = blockIdx.y * BM;
    const int n0   = blockIdx.x * BN;
    const int wm   = (wid & 3) * 32;
    const int wn   = (wid >> 2) * 64;

    const signed char* srcs[4] = {
        Ahi + (size_t)m0 * GK, Alo + (size_t)m0 * GK,
        Bhi + (size_t)n0 * GK, Blo + (size_t)n0 * GK
    };

    auto load_chunk = [&](int kt, int buf) {
        const int kc = kt * BKC;
        #pragma unroll
        for (int p = 0; p < 4; p++) {
            #pragma unroll
            for (int i = 0; i < 2; i++) {
                int id  = tid + i * 256;
                int row = id >> 2, cc = (id & 3) * 16;
                CP_ASYNC16(sb + buf * BUF_BYTES + p * TILE_BYTES + row * SLD + cc,
                           srcs[p] + (size_t)row * GK + kc + cc);
            }
        }
    };

    wmma::fragment<wmma::accumulator, 16, 16, 16, int> hh[2][4], mm[2][4];
    #pragma unroll
    for (int t = 0; t < 2; t++)
        #pragma unroll
        for (int u = 0; u < 4; u++) {
            wmma::fill_fragment(hh[t][u], 0);
            wmma::fill_fragment(mm[t][u], 0);
        }

    load_chunk(0, 0);
    CP_ASYNC_COMMIT();
    CP_ASYNC_WAIT0();
    __syncthreads();

    for (int kt = 0; kt < NKC; kt++) {
        const int cur = kt & 1;
        if (kt + 1 < NKC) {
            load_chunk(kt + 1, cur ^ 1);
            CP_ASYNC_COMMIT();
        }

        const signed char* base = sbuf + cur * BUF_BYTES;
        const signed char* pAh = base;
        const signed char* pAl = base + TILE_BYTES;
        const signed char* pBh = base + 2 * TILE_BYTES;
        const signed char* pBl = base + 3 * TILE_BYTES;

        #pragma unroll
        for (int ks = 0; ks < 4; ks++) {
            wmma::fragment<wmma::matrix_a, 16, 16, 16, signed char, wmma::row_major> ah[2], al[2];
            wmma::fragment<wmma::matrix_b, 16, 16, 16, signed char, wmma::col_major> bh[4], bl[4];
            #pragma unroll
            for (int t = 0; t < 2; t++) {
                wmma::load_matrix_sync(ah[t], pAh + (wm + t * 16) * SLD + ks * 16, SLD);
                wmma::load_matrix_sync(al[t], pAl + (wm + t * 16) * SLD + ks * 16, SLD);
            }
            #pragma unroll
            for (int u = 0; u < 4; u++) {
                wmma::load_matrix_sync(bh[u], pBh + (wn + u * 16) * SLD + ks * 16, SLD);
                wmma::load_matrix_sync(bl[u], pBl + (wn + u * 16) * SLD + ks * 16, SLD);
            }
            #pragma unroll
            for (int t = 0; t < 2; t++)
                #pragma unroll
                for (int u = 0; u < 4; u++) {
                    wmma::mma_sync(hh[t][u], ah[t], bh[u], hh[t][u]);
                    wmma::mma_sync(mm[t][u], ah[t], bl[u], mm[t][u]);
                    wmma::mma_sync(mm[t][u], al[t], bh[u], mm[t][u]);
                }
        }

        if (kt + 1 < NKC) CP_ASYNC_WAIT0();
        __syncthreads();
    }

    float* sC = (float*)smemg;
    const int CLD = 132;
    #pragma unroll
    for (int t = 0; t < 2; t++)
        #pragma unroll
        for (int u = 0; u < 4; u++) {
            wmma::fragment<wmma::accumulator, 16, 16, 16, float> ff;
            #pragma unroll
            for (int e = 0; e < ff.num_elements; e++)
                ff.x[e] = 65536.0f * (float)hh[t][u].x[e] + 256.0f * (float)mm[t][u].x[e];
            wmma::store_matrix_sync(sC + (wm + t * 16) * CLD + wn + u * 16,
                                    ff, CLD, wmma::mem_row_major);
        }
    __syncthreads();

    #pragma unroll
    for (int i = 0; i < 16; i++) {
        const int flat4 = tid + i * 256;
        const int row = flat4 >> 5;
        const int c   = (flat4 & 31) * 4;
        float v0 = sC[row * CLD + c + 0] * SCALE_OUT + bias[n0 + c + 0];
        float v1 = sC[row * CLD + c + 1] * SCALE_OUT + bias[n0 + c + 1];
        float v2 = sC[row * CLD + c + 2] * SCALE_OUT + bias[n0 + c + 2];
        float v3 = sC[row * CLD + c + 3] * SCALE_OUT + bias[n0 + c + 3];
        int h0, l0, h1, l1, h2, l2, h3, l3;
        qsplit(v0, SACT, h0, l0);
        qsplit(v1, SACT, h1, l1);
        qsplit(v2, SACT, h2, l2);
        qsplit(v3, SACT, h3, l3);
        size_t idx = (size_t)blockIdx.x * (size_t)M * 128 + (size_t)(m0 + row) * 128 + c;
        *(uint32_t*)(Chi + idx) = pack4(h0, h1, h2, h3);
        *(uint32_t*)(Clo + idx) = pack4(l0, l1, l2, l3);
    }
}

// ============================================================================
// fp16 WMMA GEMM (O projection): C = (Ahi+Alo)*Bhi^T + bias, fp32 out [M][N]
// ============================================================================
#define FTILE_ELEMS (128 * FSLD)
#define FTILE_BYTES (FTILE_ELEMS * 2)          // 18432
#define FBUF_BYTES  (3 * FTILE_BYTES)          // 55296
#define F16_GEMM_SMEM (2 * FBUF_BYTES)         // 110592

__global__ __launch_bounds__(256, 1) void gemm_f16(
    const __half* __restrict__ Ahi, const __half* __restrict__ Alo,
    const __half* __restrict__ Bhi,
    const float* __restrict__ bias, float* __restrict__ C, int M, int N)
{
    extern __shared__ char smemg[];
    __half* sbuf = (__half*)smemg;
    const uint32_t sb = smem_u32(smemg);

    const int tid  = threadIdx.x;
    const int wid  = tid >> 5;
    const int m0   = blockIdx.y * BM;
    const int n0   = blockIdx.x * BN;
    const int wm   = (wid & 3) * 32;
    const int wn   = (wid >> 2) * 64;

    const __half* srcs[3] = {
        Ahi + (size_t)m0 * GK, Alo + (size_t)m0 * GK,
        Bhi + (size_t)n0 * GK
    };

    const int lrow0 = tid >> 3;
    const int lc16  = (tid & 7) * 8;

    auto load_chunk = [&](int kt, int buf) {
        const int kc = kt * BKC;
        #pragma unroll
        for (int p = 0; p < 3; p++) {
            const __half* gsrc = srcs[p] + (size_t)lrow0 * GK + kc + lc16;
            uint32_t dst = sb + buf * FBUF_BYTES + p * FTILE_BYTES
                         + (lrow0 * FSLD + lc16) * 2;
            #pragma unroll
            for (int i = 0; i < 4; i++)
                CP_ASYNC16(dst + i * (32 * FSLD * 2), gsrc + (size_t)(i * 32) * GK);
        }
    };

    wmma::fragment<wmma::accumulator, 16, 16, 16, float> acc[2][4];
    #pragma unroll
    for (int t = 0; t < 2; t++)
        #pragma unroll
        for (int u = 0; u < 4; u++) wmma::fill_fragment(acc[t][u], 0.0f);

    load_chunk(0, 0);
    CP_ASYNC_COMMIT();
    CP_ASYNC_WAIT0();
    __syncthreads();

    for (int kt = 0; kt < NKC; kt++) {
        const int cur = kt & 1;
        if (kt + 1 < NKC) {
            load_chunk(kt + 1, cur ^ 1);
            CP_ASYNC_COMMIT();
        }

        const __half* base = sbuf + cur * (FBUF_BYTES / 2);
        const __half* pAhi = base;
        const __half* pAlo = base + FTILE_ELEMS;
        const __half* pBhi = base + 2 * FTILE_ELEMS;

        #pragma unroll
        for (int ks = 0; ks < 4; ks++) {
            wmma::fragment<wmma::matrix_a, 16, 16, 16, __half, wmma::row_major> ah[2], al[2];
            wmma::fragment<wmma::matrix_b, 16, 16, 16, __half, wmma::col_major> bh[4];
            #pragma unroll
            for (int t = 0; t < 2; t++) {
                wmma::load_matrix_sync(ah[t], pAhi + (wm + t * 16) * FSLD + ks * 16, FSLD);
                wmma::load_matrix_sync(al[t], pAlo + (wm + t * 16) * FSLD + ks * 16, FSLD);
            }
            #pragma unroll
            for (int u = 0; u < 4; u++)
                wmma::load_matrix_sync(bh[u], pBhi + (wn + u * 16) * FSLD + ks * 16, FSLD);
            #pragma unroll
            for (int t = 0; t < 2; t++)
                #pragma unroll
                for (int u = 0; u < 4; u++) {
                    wmma::mma_sync(acc[t][u], ah[t], bh[u], acc[t][u]);
                    wmma::mma_sync(acc[t][u], al[t], bh[u], acc[t][u]);
                }
        }

        if (kt + 1 < NKC) CP_ASYNC_WAIT0();
        __syncthreads();
    }

    float* sC = (float*)smemg;
    const int CLD = 132;
    #pragma unroll
    for (int t = 0; t < 2; t++)
        #pragma unroll
        for (int u = 0; u < 4; u++)
            wmma::store_matrix_sync(sC + (wm + t * 16) * CLD + wn + u * 16,
                                    acc[t][u], CLD, wmma::mem_row_major);
    __syncthreads();

    #pragma unroll
    for (int i = 0; i < 16; i++) {
        const int flat4 = tid + i * 256;
        const int row = flat4 >> 5;
        const int c   = (flat4 & 31) * 4;
        float4 o;
        o.x = sC[row * CLD + c + 0] + bias[n0 + c + 0];
        o.y = sC[row * CLD + c + 1] + bias[n0 + c + 1];
        o.z = sC[row * CLD + c + 2] + bias[n0 + c + 2];
        o.w = sC[row * CLD + c + 3] + bias[n0 + c + 3];
        *(float4*)(C + (size_t)(m0 + row) * N + n0 + c) = o;
    }
}

// ============================================================================
// IMMA flash attention: per-tile max, fp32 O accumulators, 4-term PV,
// fp16 hi/lo output.
// ============================================================================
#define AOFF_QHI 0
#define AOFF_QLO 18432
#define AOFF_KV  36864
#define KVBUF    18432
#define AOFF_S   73728
#define AOFF_PHI 108544
#define AOFF_PLO 118784
#define AOFF_SL  129024
#define AOFF_SWM 129536
#define ATTN_SMEM 129600

__global__ __launch_bounds__(256, 1) void flash_attn_imma(
    const signed char* __restrict__ Qhi, const signed char* __restrict__ Qlo,
    const signed char* __restrict__ Khi, const signed char* __restrict__ Klo,
    const signed char* __restrict__ Vhi, const signed char* __restrict__ Vlo,
    __half* __restrict__ Ohi, __half* __restrict__ Olo)
{
    extern __shared__ char smem[];
    const uint32_t sb = smem_u32(smem);

    signed char* sQh = (signed char*)(smem + AOFF_QHI);
    signed char* sQl = (signed char*)(smem + AOFF_QLO);
    float*       sS  = (float*)(smem + AOFF_S);
    signed char* sPh = (signed char*)(smem + AOFF_PHI);
    signed char* sPl = (signed char*)(smem + AOFF_PLO);
    float*       sl  = (float*)(smem + AOFF_SL);
    float*       swm = (float*)(smem + AOFF_SWM);

    const int tid = threadIdx.x;
    const int wid = tid >> 5;
    const int lane = tid & 31;
    const int qt  = gridDim.x - 1 - blockIdx.x;
    const int h   = blockIdx.y;
    const int ntiles = 2 * (qt + 1);

    const signed char* Qh_h = Qhi + ((size_t)h * S_LEN + (size_t)qt * 128) * HD;
    const signed char* Qh_l = Qlo + ((size_t)h * S_LEN + (size_t)qt * 128) * HD;
    const signed char* Kh_h = Khi + (size_t)h * S_LEN * HD;
    const signed char* Kh_l = Klo + (size_t)h * S_LEN * HD;
    const signed char* Vh_h = Vhi + (size_t)h * S_LEN * HD;
    const signed char* Vh_l = Vlo + (size_t)h * S_LEN * HD;

    auto loadQ = [&]() {
        #pragma unroll
        for (int rep = 0; rep < 4; rep++) {
            int id  = tid + rep * 256;
            int row = id >> 3, cc = (id & 7) * 16;
            CP_ASYNC16(sb + AOFF_QHI + row * 144 + cc, Qh_h + (size_t)row * HD + cc);
            CP_ASYNC16(sb + AOFF_QLO + row * 144 + cc, Qh_l + (size_t)row * HD + cc);
        }
    };
    auto loadKV = [&](const signed char* Th, const signed char* Tl,
                      int ktile, int buf) {
        const size_t base = (size_t)ktile * 64 * HD;
        #pragma unroll
        for (int rep = 0; rep < 2; rep++) {
            int id  = tid + rep * 256;
            int row = id >> 3, cc = (id & 7) * 16;
            uint32_t d = sb + AOFF_KV + buf * KVBUF + row * 144 + cc;
            CP_ASYNC16(d,        Th + base + (size_t)row * HD + cc);
            CP_ASYNC16(d + 9216, Tl + base + (size_t)row * HD + cc);
        }
    };

    loadQ();
    loadKV(Kh_h, Kh_l, 0, 0);
    CP_ASYNC_COMMIT();

    wmma::fragment<wmma::accumulator, 16, 16, 16, float> facc[2][4];
    #pragma unroll
    for (int t = 0; t < 2; t++)
        #pragma unroll
        for (int u = 0; u < 4; u++) wmma::fill_fragment(facc[t][u], 0.0f);
    float lrun = 0.0f;
    float Mrun = -1.0e30f;

    const int wm  = (wid & 3) * 32;
    const int wsn = (wid >> 2) * 32;
    const int wn  = (wid >> 2) * 64;

    for (int kt = 0; kt < ntiles; kt++) {
        const int cur = kt & 1;
        signed char* kvH = (signed char*)(smem + AOFF_KV + cur * KVBUF);
        signed char* kvL = kvH + 9216;

        CP_ASYNC_WAIT0();
        __syncthreads();

        // ---- S = Q K^T (3 IMMA terms) ----
        {
            wmma::fragment<wmma::accumulator, 16, 16, 16, int> shh[2][2], smm[2][2];
            #pragma unroll
            for (int t = 0; t < 2; t++)
                #pragma unroll
                for (int u = 0; u < 2; u++) {
                    wmma::fill_fragment(shh[t][u], 0);
                    wmma::fill_fragment(smm[t][u], 0);
                }

            #pragma unroll
            for (int ks = 0; ks < 8; ks++) {
                wmma::fragment<wmma::matrix_a, 16, 16, 16, signed char, wmma::row_major> ah[2], al[2];
                wmma::fragment<wmma::matrix_b, 16, 16, 16, signed char, wmma::col_major> bh[2], bl[2];
                #pragma unroll
                for (int t = 0; t < 2; t++) {
                    wmma::load_matrix_sync(ah[t], sQh + (wm + t * 16) * 144 + ks * 16, 144);
                    wmma::load_matrix_sync(al[t], sQl + (wm + t * 16) * 144 + ks * 16, 144);
                }
                #pragma unroll
                for (int u = 0; u < 2; u++) {
                    wmma::load_matrix_sync(bh[u], kvH + (wsn + u * 16) * 144 + ks * 16, 144);
                    wmma::load_matrix_sync(bl[u], kvL + (wsn + u * 16) * 144 + ks * 16, 144);
                }
                #pragma unroll
                for (int t = 0; t < 2; t++)
                    #pragma unroll
                    for (int u = 0; u < 2; u++) {
                        wmma::mma_sync(shh[t][u], ah[t], bh[u], shh[t][u]);
                        wmma::mma_sync(smm[t][u], ah[t], bl[u], smm[t][u]);
                        wmma::mma_sync(smm[t][u], al[t], bh[u], smm[t][u]);
                    }
            }
            #pragma unroll
            for (int t = 0; t < 2; t++)
                #pragma unroll
                for (int u = 0; u < 2; u++) {
                    wmma::fragment<wmma::accumulator, 16, 16, 16, float> ff;
                    #pragma unroll
                    for (int e = 0; e < ff.num_elements; e++)
                        ff.x[e] = 65536.0f * (float)shh[t][u].x[e]
                                + 256.0f * (float)smm[t][u].x[e];
                    wmma::store_matrix_sync(sS + (wm + t * 16) * 68 + wsn + u * 16,
                                            ff, 68, wmma::mem_row_major);
                }
        }
        __syncthreads();

        // ---- prefetch ----
        loadKV(Vh_h, Vh_l, kt, cur);
        CP_ASYNC_COMMIT();
        if (kt + 1 < ntiles) loadKV(Kh_h, Kh_l, kt + 1, cur ^ 1);
        CP_ASYNC_COMMIT();

        // ---- tile max ----
        {
            const float* Srow = sS + (tid >> 1) * 68 + (tid & 1) * 32;
            float lm = -1.0e30f;
            #pragma unroll
            for (int j = 0; j < 32; j++) lm = fmaxf(lm, Srow[j]);
            #pragma unroll
            for (int o = 16; o > 0; o >>= 1)
                lm = fmaxf(lm, __shfl_xor_sync(0xffffffffu, lm, o));
            if (lane == 0) swm[wid] = lm;
        }
        __syncthreads();
        float mfs = swm[0];
        #pragma unroll
        for (int w = 1; w < 8; w++) mfs = fmaxf(mfs, swm[w]);
        const float m_sc = mfs * SLOGIT;
        const float Mnew = fmaxf(Mrun, m_sc);
        const float corr = __expf(Mrun - Mnew);
        const float gam  = __expf(m_sc - Mnew);
        Mrun = Mnew;

        // ---- softmax + quantize ----
        {
            const int row = tid >> 1;
            const int c0  = (tid & 1) * 32;
            const int qglob = qt * 128 + row;
            const int kbase = kt * 64 + c0;
            const bool needMask = (kt >= 2 * qt);
            const float* Srow = sS + row * 68 + c0;
            signed char* Ph = sPh + row * 80 + c0;
            signed char* Pl = sPl + row * 80 + c0;
            float psum = 0.0f;
            #pragma unroll
            for (int j = 0; j < 32; j += 4) {
                int qh[4], ql[4];
                #pragma unroll
                for (int e = 0; e < 4; e++) {
                    float p = __expf(Srow[j + e] * SLOGIT - m_sc);
                    if (needMask && (kbase + j + e > qglob)) p = 0.0f;
                    int q = __float2int_rn(p * PSCALE);
                    psum += (float)q;
                    ql[e] = (int)((unsigned)(q + 128) & 255u) - 128;
                    qh[e] = (q - ql[e]) >> 8;
                }
                *(uint32_t*)(Ph + j) = pack4(qh[0], qh[1], qh[2], qh[3]);
                *(uint32_t*)(Pl + j) = pack4(ql[0], ql[1], ql[2], ql[3]);
            }
            psum += __shfl_xor_sync(0xffffffffu, psum, 1);
            lrun = lrun * corr + psum * gam;
        }

        CP_ASYNC_WAIT1();
        __syncthreads();

        // ---- O += P V (4 IMMA terms), fold into fp32 accum ----
        #pragma unroll
        for (int half = 0; half < 2; half++) {
            wmma::fragment<wmma::accumulator, 16, 16, 16, int> phh[2][2], pmm[2][2], pll[2][2];
            #pragma unroll
            for (int t = 0; t < 2; t++)
                #pragma unroll
                for (int u = 0; u < 2; u++) {
                    wmma::fill_fragment(phh[t][u], 0);
                    wmma::fill_fragment(pmm[t][u], 0);
                    wmma::fill_fragment(pll[t][u], 0);
                }
            #pragma unroll
            for (int ks = 0; ks < 4; ks++) {
                wmma::fragment<wmma::matrix_a, 16, 16, 16, signed char, wmma::row_major> ph[2], pl[2];
                wmma::fragment<wmma::matrix_b, 16, 16, 16, signed char, wmma::row_major> vh[2], vl[2];
                #pragma unroll
                for (int t = 0; t < 2; t++) {
                    wmma::load_matrix_sync(ph[t], sPh + (wm + t * 16) * 80 + ks * 16, 80);
                    wmma::load_matrix_sync(pl[t], sPl + (wm + t * 16) * 80 + ks * 16, 80);
                }
                #pragma unroll
                for (int u = 0; u < 2; u++) {
                    const int col = wn + half * 32 + u * 16;
                    wmma::load_matrix_sync(vh[u], kvH + (ks * 16) * 144 + col, 144);
                    wmma::load_matrix_sync(vl[u], kvL + (ks * 16) * 144 + col, 144);
                }
                #pragma unroll
                for (int t = 0; t < 2; t++)
                    #pragma unroll
                    for (int u = 0; u < 2; u++) {
                        wmma::mma_sync(phh[t][u], ph[t], vh[u], phh[t][u]);
                        wmma::mma_sync(pmm[t][u], ph[t], vl[u], pmm[t][u]);
                        wmma::mma_sync(pmm[t][u], pl[t], vh[u], pmm[t][u]);
                        wmma::mma_sync(pll[t][u], pl[t], vl[u], pll[t][u]);
                    }
            }
            #pragma unroll
            for (int t = 0; t < 2; t++)
                #pragma unroll
                for (int u = 0; u < 2; u++) {
                    const int uu = half * 2 + u;
                    #pragma unroll
                    for (int e = 0; e < facc[t][uu].num_elements; e++)
                        facc[t][uu].x[e] = facc[t][uu].x[e] * corr
                            + (65536.0f * (float)phh[t][u].x[e]
                               + 256.0f * (float)pmm[t][u].x[e]
                               + (float)pll[t][u].x[e]) * gam;
                }
        }
    }

    CP_ASYNC_WAIT0();
    __syncthreads();

    // ---- epilogue: O = facc / (lrun * SACT), fp16 hi/lo, write ----
    float* sO = (float*)(smem + AOFF_KV);
    const int OLD = 132;
    #pragma unroll
    for (int t = 0; t < 2; t++)
        #pragma unroll
        for (int u = 0; u < 4; u++)
            wmma::store_matrix_sync(sO + (wm + t * 16) * OLD + wn + u * 16,
                                    facc[t][u], OLD, wmma::mem_row_major);
    if ((tid & 1) == 0) sl[tid >> 1] = lrun;
    __syncthreads();

    {
        const int row = tid >> 1;
        const int c0  = (tid & 1) * 64;
        const float inv = (1.0f / SACT) / sl[row];
        const size_t dbase = (size_t)(qt * 128 + row) * DIM + (size_t)h * HD + c0;
        #pragma unroll
        for (int j = 0; j < 64; j += 2) {
            float o0 = sO[row * OLD + c0 + j]     * inv;
            float o1 = sO[row * OLD + c0 + j + 1] * inv;
            __half h0 = __float2half(o0);
            __half h1 = __float2half(o1);
            *(uint32_t*)(Ohi + dbase + j) = pack_h2(h0, h1);
            *(uint32_t*)(Olo + dbase + j) = pack_h2(
                __float2half(o0 - __half2float(h0)),
                __float2half(o1 - __half2float(h1)));
        }
    }
}

// ============================================================================
// launch
// ============================================================================
extern "C" void kernel_launch(void* const* d_in, const int* in_sizes, int n_in,
                              void* d_out, int out_size)
{
    const float* X  = (const float*)d_in[0];
    const float* Wq = (const float*)d_in[1];
    const float* bq = (const float*)d_in[2];
    const float* Wk = (const float*)d_in[3];
    const float* bk = (const float*)d_in[4];
    const float* Wv = (const float*)d_in[5];
    const float* bv = (const float*)d_in[6];
    const float* Wo = (const float*)d_in[7];
    const float* bo = (const float*)d_in[8];

    signed char *Qhi, *Qlo, *Khi, *Klo, *Vhi, *Vlo, *Xhi, *Xlo, *Whi, *Wlo;
    __half *Ohi, *Olo, *Wo16;
    cudaGetSymbolAddress((void**)&Qhi, g_Qhi);
    cudaGetSymbolAddress((void**)&Qlo, g_Qlo);
    cudaGetSymbolAddress((void**)&Khi, g_Khi);
    cudaGetSymbolAddress((void**)&Klo, g_Klo);
    cudaGetSymbolAddress((void**)&Vhi, g_Vhi);
    cudaGetSymbolAddress((void**)&Vlo, g_Vlo);
    cudaGetSymbolAddress((void**)&Xhi, g_Xhi);
    cudaGetSymbolAddress((void**)&Xlo, g_Xlo);
    cudaGetSymbolAddress((void**)&Whi, g_Whi);
    cudaGetSymbolAddress((void**)&Wlo, g_Wlo);
    cudaGetSymbolAddress((void**)&Ohi, g_Ohi);
    cudaGetSymbolAddress((void**)&Olo, g_Olo);
    cudaGetSymbolAddress((void**)&Wo16, g_Wo16);

    const int NX4 = S_LEN * DIM / 4;
    const int NW4 = DIM * DIM / 4;

    split8<<<(NX4 + 255) / 256, 256>>>((const float4*)X,
        (uint32_t*)Xhi, (uint32_t*)Xlo, NX4, SACT);
    const float* Ws[3] = {Wq, Wk, Wv};
    for (int w = 0; w < 3; w++)
        split8<<<(NW4 + 255) / 256, 256>>>((const float4*)Ws[w],
            (uint32_t*)(Whi + (size_t)w * DIM * DIM),
            (uint32_t*)(Wlo + (size_t)w * DIM * DIM), NW4, SWGT);
    split_h16<<<(NW4 + 255) / 256, 256>>>((const float4*)Wo, (uint2*)Wo16, NW4);

    cudaFuncSetAttribute(gemm_imma,
        cudaFuncAttributeMaxDynamicSharedMemorySize, GEMM_SMEM);
    cudaFuncSetAttribute(gemm_f16,
        cudaFuncAttributeMaxDynamicSharedMemorySize, F16_GEMM_SMEM);
    cudaFuncSetAttribute(flash_attn_imma,
        cudaFuncAttributeMaxDynamicSharedMemorySize, ATTN_SMEM);

    const dim3 gGemm(DIM / BN, S_LEN / BM);

    gemm_imma<<<gGemm, 256, GEMM_SMEM>>>(Xhi, Xlo,
        Whi + 0 * (size_t)DIM * DIM, Wlo + 0 * (size_t)DIM * DIM, bq,
        Qhi, Qlo, S_LEN, DIM);
    gemm_imma<<<gGemm, 256, GEMM_SMEM>>>(Xhi, Xlo,
        Whi + 1 * (size_t)DIM * DIM, Wlo + 1 * (size_t)DIM * DIM, bk,
        Khi, Klo, S_LEN, DIM);
    gemm_imma<<<gGemm, 256, GEMM_SMEM>>>(Xhi, Xlo,
        Whi + 2 * (size_t)DIM * DIM, Wlo + 2 * (size_t)DIM * DIM, bv,
        Vhi, Vlo, S_LEN, DIM);

    dim3 gAttn(S_LEN / 128, HEADS);
    flash_attn_imma<<<gAttn, 256, ATTN_SMEM>>>(Qhi, Qlo, Khi, Klo, Vhi, Vlo, Ohi, Olo);

    gemm_f16<<<gGemm, 256, F16_GEMM_SMEM>>>(Ohi, Olo, Wo16, bo,
        (float*)d_out, S_LEN, DIM);
}

// round 10
// speedup vs baseline: 7.6840x; 7.6840x over previous
#include <cuda_runtime.h>
#include <cuda_fp16.h>
#include <mma.h>
#include <math_constants.h>
#include <cstdint>

using namespace nvcuda;

#define S_LEN 4096
#define DIM   2048
#define HEADS 16
#define HD    128
#define GK    2048
#define BM    128
#define BN    128
#define BKC   64
#define NKC   (GK / BKC)    // 32
#define FSLD  72            // gemm smem row stride (fp16)

// ---------------- scratch (allocation-free rule: __device__ globals) ----------
__device__ __half g_Q16[HEADS * S_LEN * HD];
__device__ __half g_K16[HEADS * S_LEN * HD];
__device__ __half g_V16[HEADS * S_LEN * HD];
__device__ __half g_Ohi[S_LEN * DIM];
__device__ __half g_Olo[S_LEN * DIM];
__device__ __half g_Xhi[S_LEN * DIM];
__device__ __half g_Xlo[S_LEN * DIM];
__device__ __half g_W16[4][DIM * DIM];

// ---------------- helpers ------------------------------------------------------
__device__ __forceinline__ uint32_t smem_u32(const void* p) {
    uint32_t a;
    asm("{ .reg .u64 t; cvta.to.shared.u64 t, %1; cvt.u32.u64 %0, t; }"
        : "=r"(a) : "l"(p));
    return a;
}
#define CP_ASYNC16(dst_u32, src_ptr) \
    asm volatile("cp.async.cg.shared.global [%0], [%1], 16;" \
        :: "r"(dst_u32), "l"(src_ptr) : "memory")
#define CP_ASYNC_COMMIT() asm volatile("cp.async.commit_group;" ::: "memory")
#define CP_ASYNC_WAIT0()  asm volatile("cp.async.wait_group 0;" ::: "memory")
#define CP_ASYNC_WAIT1()  asm volatile("cp.async.wait_group 1;" ::: "memory")

__device__ __forceinline__ uint32_t pack_h2(__half a, __half b) {
    __half2 t = __halves2half2(a, b);
    return *(uint32_t*)&t;
}

// ============================================================================
// splits
// ============================================================================
__global__ void split_hi_lo(const float4* __restrict__ src,
                            uint2* __restrict__ hi, uint2* __restrict__ lo,
                            int n4) {
    int i = blockIdx.x * 256 + threadIdx.x;
    if (i >= n4) return;
    float4 v = src[i];
    __half h0 = __float2half(v.x), h1 = __float2half(v.y);
    __half h2 = __float2half(v.z), h3 = __float2half(v.w);
    uint2 ho;
    ho.x = pack_h2(h0, h1);  ho.y = pack_h2(h2, h3);
    hi[i] = ho;
    uint2 lo2;
    lo2.x = pack_h2(__float2half(v.x - __half2float(h0)),
                    __float2half(v.y - __half2float(h1)));
    lo2.y = pack_h2(__float2half(v.z - __half2float(h2)),
                    __float2half(v.w - __half2float(h3)));
    lo[i] = lo2;
}

__global__ void split_h16(const float4* __restrict__ src,
                          uint2* __restrict__ hi, int n4) {
    int i = blockIdx.x * 256 + threadIdx.x;
    if (i >= n4) return;
    float4 v = src[i];
    uint2 ho;
    ho.x = pack_h2(__float2half(v.x), __float2half(v.y));
    ho.y = pack_h2(__float2half(v.z), __float2half(v.w));
    hi[i] = ho;
}

// ============================================================================
// fp16 WMMA GEMM: C = (Ahi [+ Alo]) * B^T + bias
//   ATERMS: 1 or 2 A-operand terms.
//   MODE 0: C fp32 [M][N]
//   MODE 1: C fp16 single-rounded, head layout [N/128][M][128]
// ============================================================================
#define FTILE_ELEMS (128 * FSLD)
#define FTILE_BYTES (FTILE_ELEMS * 2)          // 18432
#define F16_GEMM_SMEM_MAX (2 * 3 * FTILE_BYTES) // 110592

template <int ATERMS, int MODE>
__global__ __launch_bounds__(256, 1) void gemm_f16(
    const __half* __restrict__ Ahi, const __half* __restrict__ Alo,
    const __half* __restrict__ B,
    const float* __restrict__ bias, float* __restrict__ C,
    __half* __restrict__ Ch, int M, int N)
{
    constexpr int TILES = ATERMS + 1;
    constexpr int BUFB  = TILES * FTILE_BYTES;

    extern __shared__ char smemg[];
    __half* sbuf = (__half*)smemg;
    const uint32_t sb = smem_u32(smemg);

    const int tid  = threadIdx.x;
    const int wid  = tid >> 5;
    const int m0   = blockIdx.y * BM;
    const int n0   = blockIdx.x * BN;
    const int wm   = (wid & 3) * 32;
    const int wn   = (wid >> 2) * 64;

    const __half* srcs[TILES];
    srcs[0] = Ahi + (size_t)m0 * GK;
    if (ATERMS == 2) srcs[1] = Alo + (size_t)m0 * GK;
    srcs[TILES - 1] = B + (size_t)n0 * GK;

    const int lrow0 = tid >> 3;
    const int lc16  = (tid & 7) * 8;

    auto load_chunk = [&](int kt, int buf) {
        const int kc = kt * BKC;
        #pragma unroll
        for (int p = 0; p < TILES; p++) {
            const __half* gsrc = srcs[p] + (size_t)lrow0 * GK + kc + lc16;
            uint32_t dst = sb + buf * BUFB + p * FTILE_BYTES
                         + (lrow0 * FSLD + lc16) * 2;
            #pragma unroll
            for (int i = 0; i < 4; i++)
                CP_ASYNC16(dst + i * (32 * FSLD * 2), gsrc + (size_t)(i * 32) * GK);
        }
    };

    wmma::fragment<wmma::accumulator, 16, 16, 16, float> acc[2][4];
    #pragma unroll
    for (int t = 0; t < 2; t++)
        #pragma unroll
        for (int u = 0; u < 4; u++) wmma::fill_fragment(acc[t][u], 0.0f);

    load_chunk(0, 0);
    CP_ASYNC_COMMIT();
    CP_ASYNC_WAIT0();
    __syncthreads();

    for (int kt = 0; kt < NKC; kt++) {
        const int cur = kt & 1;
        if (kt + 1 < NKC) {
            load_chunk(kt + 1, cur ^ 1);
            CP_ASYNC_COMMIT();
        }

        const __half* base = sbuf + cur * (BUFB / 2);
        const __half* pAhi = base;
        const __half* pAlo = base + FTILE_ELEMS;          // valid iff ATERMS==2
        const __half* pB   = base + (TILES - 1) * FTILE_ELEMS;

        #pragma unroll
        for (int ks = 0; ks < 4; ks++) {
            wmma::fragment<wmma::matrix_a, 16, 16, 16, __half, wmma::row_major> ah[2], al[2];
            wmma::fragment<wmma::matrix_b, 16, 16, 16, __half, wmma::col_major> bh[4];
            #pragma unroll
            for (int t = 0; t < 2; t++) {
                wmma::load_matrix_sync(ah[t], pAhi + (wm + t * 16) * FSLD + ks * 16, FSLD);
                if (ATERMS == 2)
                    wmma::load_matrix_sync(al[t], pAlo + (wm + t * 16) * FSLD + ks * 16, FSLD);
            }
            #pragma unroll
            for (int u = 0; u < 4; u++)
                wmma::load_matrix_sync(bh[u], pB + (wn + u * 16) * FSLD + ks * 16, FSLD);
            #pragma unroll
            for (int t = 0; t < 2; t++)
                #pragma unroll
                for (int u = 0; u < 4; u++) {
                    wmma::mma_sync(acc[t][u], ah[t], bh[u], acc[t][u]);
                    if (ATERMS == 2)
                        wmma::mma_sync(acc[t][u], al[t], bh[u], acc[t][u]);
                }
        }

        if (kt + 1 < NKC) CP_ASYNC_WAIT0();
        __syncthreads();
    }

    float* sC = (float*)smemg;
    const int CLD = 132;
    #pragma unroll
    for (int t = 0; t < 2; t++)
        #pragma unroll
        for (int u = 0; u < 4; u++)
            wmma::store_matrix_sync(sC + (wm + t * 16) * CLD + wn + u * 16,
                                    acc[t][u], CLD, wmma::mem_row_major);
    __syncthreads();

    #pragma unroll
    for (int i = 0; i < 16; i++) {
        const int flat4 = tid + i * 256;
        const int row = flat4 >> 5;
        const int c   = (flat4 & 31) * 4;
        float v0 = sC[row * CLD + c + 0] + bias[n0 + c + 0];
        float v1 = sC[row * CLD + c + 1] + bias[n0 + c + 1];
        float v2 = sC[row * CLD + c + 2] + bias[n0 + c + 2];
        float v3 = sC[row * CLD + c + 3] + bias[n0 + c + 3];
        if (MODE == 0) {
            *(float4*)(C + (size_t)(m0 + row) * N + n0 + c) =
                make_float4(v0, v1, v2, v3);
        } else {
            size_t idx = (size_t)blockIdx.x * (size_t)M * 128 + (size_t)(m0 + row) * 128 + c;
            uint2 ho;
            ho.x = pack_h2(__float2half(v0), __float2half(v1));
            ho.y = pack_h2(__float2half(v2), __float2half(v3));
            *(uint2*)(Ch + idx) = ho;
        }
    }
}

// ============================================================================
// fp16 WMMA flash attention (causal): single-term S and PV, per-tile max,
// online corr on fp32 fragment accumulators, fp16 hi/lo output.
//   CTA: 128 queries x 1 head; 64-key tiles; 8 warps.
// SMEM (bytes):
//   Q  fp16 [128][136] @0          (34816)
//   KV bufs: [64][136] fp16 @34816 + b*17408   (34816)
//   S  fp32 [128][68]  @69632      (34816)
//   P  fp16 [128][72]  @104448     (18432)
//   sl @122880 (512), swm @123392 (32)
// Epilogue fp32 O [128][132] (67584) aliases @34816.
// ============================================================================
#define AQ_OFF  0
#define AKV_OFF 34816
#define KVBUF   17408
#define AS_OFF  69632
#define AP_OFF  104448
#define ASL_OFF 122880
#define ASW_OFF 123392
#define ATTN_SMEM 123424
#define QKSCALE 0.08838834764831843f   // 1/sqrt(128)

__global__ __launch_bounds__(256, 1) void flash_attn_f16(
    const __half* __restrict__ Q16, const __half* __restrict__ K16,
    const __half* __restrict__ V16,
    __half* __restrict__ Ohi, __half* __restrict__ Olo)
{
    extern __shared__ char smem[];
    const uint32_t sb = smem_u32(smem);

    __half* sQ  = (__half*)(smem + AQ_OFF);
    float*  sS  = (float*)(smem + AS_OFF);
    __half* sP  = (__half*)(smem + AP_OFF);
    float*  sl  = (float*)(smem + ASL_OFF);
    float*  swm = (float*)(smem + ASW_OFF);

    const int tid = threadIdx.x;
    const int wid = tid >> 5;
    const int lane = tid & 31;
    const int qt  = gridDim.x - 1 - blockIdx.x;   // heavy CTAs first
    const int h   = blockIdx.y;
    const int ntiles = 2 * (qt + 1);

    const __half* Qh = Q16 + ((size_t)h * S_LEN + (size_t)qt * 128) * HD;
    const __half* Kh = K16 + (size_t)h * S_LEN * HD;
    const __half* Vh = V16 + (size_t)h * S_LEN * HD;

    auto loadQ = [&]() {
        #pragma unroll
        for (int rep = 0; rep < 8; rep++) {
            int id  = tid + rep * 256;            // 0..2047
            int row = id >> 4, cc = (id & 15) * 8;
            CP_ASYNC16(sb + AQ_OFF + (row * 136 + cc) * 2, Qh + (size_t)row * HD + cc);
        }
    };
    auto loadKV = [&](const __half* Tp, int ktile, int buf) {
        const size_t base = (size_t)ktile * 64 * HD;
        #pragma unroll
        for (int rep = 0; rep < 4; rep++) {
            int id  = tid + rep * 256;            // 0..1023
            int row = id >> 4, cc = (id & 15) * 8;
            CP_ASYNC16(sb + AKV_OFF + buf * KVBUF + (row * 136 + cc) * 2,
                       Tp + base + (size_t)row * HD + cc);
        }
    };

    loadQ();
    loadKV(Kh, 0, 0);
    CP_ASYNC_COMMIT();

    wmma::fragment<wmma::accumulator, 16, 16, 16, float> facc[2][4];
    #pragma unroll
    for (int t = 0; t < 2; t++)
        #pragma unroll
        for (int u = 0; u < 4; u++) wmma::fill_fragment(facc[t][u], 0.0f);
    float lrun = 0.0f;
    float Mrun = -1.0e30f;

    const int wm  = (wid & 3) * 32;       // warp q-rows
    const int wsn = (wid >> 2) * 32;      // warp key-cols (S phase)
    const int wn  = (wid >> 2) * 64;      // warp d-cols (PV phase)

    for (int kt = 0; kt < ntiles; kt++) {
        const int cur = kt & 1;
        __half* kvS = (__half*)(smem + AKV_OFF + cur * KVBUF);

        CP_ASYNC_WAIT0();
        __syncthreads();

        // ---- S = Q K^T (single term) ----
        {
            wmma::fragment<wmma::accumulator, 16, 16, 16, float> accs[2][2];
            #pragma unroll
            for (int t = 0; t < 2; t++)
                #pragma unroll
                for (int u = 0; u < 2; u++) wmma::fill_fragment(accs[t][u], 0.0f);

            #pragma unroll
            for (int ks = 0; ks < 8; ks++) {
                wmma::fragment<wmma::matrix_a, 16, 16, 16, __half, wmma::row_major> ah[2];
                wmma::fragment<wmma::matrix_b, 16, 16, 16, __half, wmma::col_major> bh[2];
                #pragma unroll
                for (int t = 0; t < 2; t++)
                    wmma::load_matrix_sync(ah[t], sQ + (wm + t * 16) * 136 + ks * 16, 136);
                #pragma unroll
                for (int u = 0; u < 2; u++)
                    wmma::load_matrix_sync(bh[u], kvS + (wsn + u * 16) * 136 + ks * 16, 136);
                #pragma unroll
                for (int t = 0; t < 2; t++)
                    #pragma unroll
                    for (int u = 0; u < 2; u++)
                        wmma::mma_sync(accs[t][u], ah[t], bh[u], accs[t][u]);
            }
            #pragma unroll
            for (int t = 0; t < 2; t++)
                #pragma unroll
                for (int u = 0; u < 2; u++)
                    wmma::store_matrix_sync(sS + (wm + t * 16) * 68 + wsn + u * 16,
                                            accs[t][u], 68, wmma::mem_row_major);
        }
        __syncthreads();

        // ---- prefetch: V(kt) overwrites K(kt) in buf cur; K(kt+1) -> other buf
        loadKV(Vh, kt, cur);
        CP_ASYNC_COMMIT();
        if (kt + 1 < ntiles) loadKV(Kh, kt + 1, cur ^ 1);
        CP_ASYNC_COMMIT();

        // ---- tile max (CTA-wide, on scaled logits) ----
        {
            const float* Srow = sS + (tid >> 1) * 68 + (tid & 1) * 32;
            float lm = -1.0e30f;
            #pragma unroll
            for (int j = 0; j < 32; j++) lm = fmaxf(lm, Srow[j]);
            #pragma unroll
            for (int o = 16; o > 0; o >>= 1)
                lm = fmaxf(lm, __shfl_xor_sync(0xffffffffu, lm, o));
            if (lane == 0) swm[wid] = lm;
        }
        __syncthreads();
        float mfs = swm[0];
        #pragma unroll
        for (int w = 1; w < 8; w++) mfs = fmaxf(mfs, swm[w]);
        const float m_sc = mfs * QKSCALE;
        const float Mnew = fmaxf(Mrun, m_sc);
        const float corr = __expf(Mrun - Mnew);
        Mrun = Mnew;

        // ---- softmax: p = exp(s*scale - Mnew), mask, fp16 store ----
        {
            const int row = tid >> 1;
            const int c0  = (tid & 1) * 32;
            const int qglob = qt * 128 + row;
            const int kbase = kt * 64 + c0;
            const bool needMask = (kt >= 2 * qt);
            const float* Srow = sS + row * 68 + c0;
            __half* Pr = sP + row * 72 + c0;
            float psum = 0.0f;
            #pragma unroll
            for (int j = 0; j < 32; j += 2) {
                float p0 = __expf(Srow[j]     * QKSCALE - Mnew);
                float p1 = __expf(Srow[j + 1] * QKSCALE - Mnew);
                if (needMask) {
                    if (kbase + j     > qglob) p0 = 0.0f;
                    if (kbase + j + 1 > qglob) p1 = 0.0f;
                }
                psum += p0 + p1;
                *(uint32_t*)(Pr + j) = pack_h2(__float2half(p0), __float2half(p1));
            }
            psum += __shfl_xor_sync(0xffffffffu, psum, 1);
            lrun = lrun * corr + psum;
        }

        // ---- rescale persistent accumulators by corr (overlap with V load) --
        #pragma unroll
        for (int t = 0; t < 2; t++)
            #pragma unroll
            for (int u = 0; u < 4; u++)
                #pragma unroll
                for (int e = 0; e < facc[t][u].num_elements; e++)
                    facc[t][u].x[e] *= corr;

        CP_ASYNC_WAIT1();          // V ready (K may still be in flight)
        __syncthreads();           // P visible to all warps

        // ---- O += P V (single term, direct fp32 accumulation) ----
        #pragma unroll
        for (int ks = 0; ks < 4; ks++) {
            wmma::fragment<wmma::matrix_a, 16, 16, 16, __half, wmma::row_major> pa[2];
            wmma::fragment<wmma::matrix_b, 16, 16, 16, __half, wmma::row_major> vb[4];
            #pragma unroll
            for (int t = 0; t < 2; t++)
                wmma::load_matrix_sync(pa[t], sP + (wm + t * 16) * 72 + ks * 16, 72);
            #pragma unroll
            for (int u = 0; u < 4; u++)
                wmma::load_matrix_sync(vb[u], kvS + (ks * 16) * 136 + wn + u * 16, 136);
            #pragma unroll
            for (int t = 0; t < 2; t++)
                #pragma unroll
                for (int u = 0; u < 4; u++)
                    wmma::mma_sync(facc[t][u], pa[t], vb[u], facc[t][u]);
        }
    }

    CP_ASYNC_WAIT0();
    __syncthreads();

    // ---- epilogue: O = facc / lrun, fp16 hi/lo, write [s][DIM] ----
    float* sO = (float*)(smem + AKV_OFF);     // [128][132] fp32
    const int OLD = 132;
    #pragma unroll
    for (int t = 0; t < 2; t++)
        #pragma unroll
        for (int u = 0; u < 4; u++)
            wmma::store_matrix_sync(sO + (wm + t * 16) * OLD + wn + u * 16,
                                    facc[t][u], OLD, wmma::mem_row_major);
    if ((tid & 1) == 0) sl[tid >> 1] = lrun;
    __syncthreads();

    {
        const int row = tid >> 1;
        const int c0  = (tid & 1) * 64;
        const float inv = 1.0f / sl[row];
        const size_t dbase = (size_t)(qt * 128 + row) * DIM + (size_t)h * HD + c0;
        #pragma unroll
        for (int j = 0; j < 64; j += 2) {
            float o0 = sO[row * OLD + c0 + j]     * inv;
            float o1 = sO[row * OLD + c0 + j + 1] * inv;
            __half h0 = __float2half(o0);
            __half h1 = __float2half(o1);
            *(uint32_t*)(Ohi + dbase + j) = pack_h2(h0, h1);
            *(uint32_t*)(Olo + dbase + j) = pack_h2(
                __float2half(o0 - __half2float(h0)),
                __float2half(o1 - __half2float(h1)));
        }
    }
}

// ============================================================================
// launch
// ============================================================================
extern "C" void kernel_launch(void* const* d_in, const int* in_sizes, int n_in,
                              void* d_out, int out_size)
{
    const float* X  = (const float*)d_in[0];
    const float* Wq = (const float*)d_in[1];
    const float* bq = (const float*)d_in[2];
    const float* Wk = (const float*)d_in[3];
    const float* bk = (const float*)d_in[4];
    const float* Wv = (const float*)d_in[5];
    const float* bv = (const float*)d_in[6];
    const float* Wo = (const float*)d_in[7];
    const float* bo = (const float*)d_in[8];

    __half *Q16, *K16, *V16, *Ohi, *Olo, *Xhi, *Xlo, *W16;
    cudaGetSymbolAddress((void**)&Q16, g_Q16);
    cudaGetSymbolAddress((void**)&K16, g_K16);
    cudaGetSymbolAddress((void**)&V16, g_V16);
    cudaGetSymbolAddress((void**)&Ohi, g_Ohi);
    cudaGetSymbolAddress((void**)&Olo, g_Olo);
    cudaGetSymbolAddress((void**)&Xhi, g_Xhi);
    cudaGetSymbolAddress((void**)&Xlo, g_Xlo);
    cudaGetSymbolAddress((void**)&W16, g_W16);

    const int NX4 = S_LEN * DIM / 4;
    const int NW4 = DIM * DIM / 4;

    split_hi_lo<<<(NX4 + 255) / 256, 256>>>((const float4*)X,
        (uint2*)Xhi, (uint2*)Xlo, NX4);
    const float* Ws[4] = {Wq, Wk, Wv, Wo};
    for (int w = 0; w < 4; w++)
        split_h16<<<(NW4 + 255) / 256, 256>>>((const float4*)Ws[w],
            (uint2*)(W16 + (size_t)w * DIM * DIM), NW4);

    cudaFuncSetAttribute(gemm_f16<1, 1>,
        cudaFuncAttributeMaxDynamicSharedMemorySize, F16_GEMM_SMEM_MAX);
    cudaFuncSetAttribute(gemm_f16<2, 1>,
        cudaFuncAttributeMaxDynamicSharedMemorySize, F16_GEMM_SMEM_MAX);
    cudaFuncSetAttribute(gemm_f16<2, 0>,
        cudaFuncAttributeMaxDynamicSharedMemorySize, F16_GEMM_SMEM_MAX);
    cudaFuncSetAttribute(flash_attn_f16,
        cudaFuncAttributeMaxDynamicSharedMemorySize, ATTN_SMEM);

    const dim3 gGemm(DIM / BN, S_LEN / BM);   // (16, 32)
    const int smem1 = 2 * 2 * FTILE_BYTES;    // ATERMS=1
    const int smem2 = 2 * 3 * FTILE_BYTES;    // ATERMS=2

    // Q, K projections: 1-term (logit path, error attenuated)
    gemm_f16<1, 1><<<gGemm, 256, smem1>>>(Xhi, nullptr,
        W16 + 0 * (size_t)DIM * DIM, bq, nullptr, Q16, S_LEN, DIM);
    gemm_f16<1, 1><<<gGemm, 256, smem1>>>(Xhi, nullptr,
        W16 + 1 * (size_t)DIM * DIM, bk, nullptr, K16, S_LEN, DIM);
    // V projection: 2-term (direct path)
    gemm_f16<2, 1><<<gGemm, 256, smem2>>>(Xhi, Xlo,
        W16 + 2 * (size_t)DIM * DIM, bv, nullptr, V16, S_LEN, DIM);

    dim3 gAttn(S_LEN / 128, HEADS);
    flash_attn_f16<<<gAttn, 256, ATTN_SMEM>>>(Q16, K16, V16, Ohi, Olo);

    // O projection: 2-term (direct path)
    gemm_f16<2, 0><<<gGemm, 256, smem2>>>(Ohi, Olo,
        W16 + 3 * (size_t)DIM * DIM, bo, (float*)d_out, nullptr, S_LEN, DIM);
}

// round 11
// speedup vs baseline: 8.5517x; 1.1129x over previous
#include <cuda_runtime.h>
#include <cuda_fp16.h>
#include <mma.h>
#include <math_constants.h>
#include <cstdint>

using namespace nvcuda;

#define S_LEN 4096
#define DIM   2048
#define HEADS 16
#define HD    128
#define GK    2048
#define BM    128
#define BN    128
#define BKC   64
#define NKC   (GK / BKC)    // 32
#define FSLD  72            // gemm smem row stride (fp16)

// ---------------- scratch (allocation-free rule: __device__ globals) ----------
__device__ __half g_Q16[HEADS * S_LEN * HD];
__device__ __half g_K16[HEADS * S_LEN * HD];
__device__ __half g_V16[HEADS * S_LEN * HD];
__device__ __half g_O16[S_LEN * DIM];
__device__ __half g_Xhi[S_LEN * DIM];
__device__ __half g_Xlo[S_LEN * DIM];
__device__ __half g_W16[4][DIM * DIM];

// ---------------- helpers ------------------------------------------------------
__device__ __forceinline__ uint32_t smem_u32(const void* p) {
    uint32_t a;
    asm("{ .reg .u64 t; cvta.to.shared.u64 t, %1; cvt.u32.u64 %0, t; }"
        : "=r"(a) : "l"(p));
    return a;
}
#define CP_ASYNC16(dst_u32, src_ptr) \
    asm volatile("cp.async.cg.shared.global [%0], [%1], 16;" \
        :: "r"(dst_u32), "l"(src_ptr) : "memory")
#define CP_ASYNC_COMMIT() asm volatile("cp.async.commit_group;" ::: "memory")
#define CP_ASYNC_WAIT0()  asm volatile("cp.async.wait_group 0;" ::: "memory")
#define CP_ASYNC_WAIT1()  asm volatile("cp.async.wait_group 1;" ::: "memory")

__device__ __forceinline__ uint32_t pack_h2(__half a, __half b) {
    __half2 t = __halves2half2(a, b);
    return *(uint32_t*)&t;
}

// ============================================================================
// splits
// ============================================================================
__global__ void split_hi_lo(const float4* __restrict__ src,
                            uint2* __restrict__ hi, uint2* __restrict__ lo,
                            int n4) {
    int i = blockIdx.x * 256 + threadIdx.x;
    if (i >= n4) return;
    float4 v = src[i];
    __half h0 = __float2half(v.x), h1 = __float2half(v.y);
    __half h2 = __float2half(v.z), h3 = __float2half(v.w);
    uint2 ho;
    ho.x = pack_h2(h0, h1);  ho.y = pack_h2(h2, h3);
    hi[i] = ho;
    uint2 lo2;
    lo2.x = pack_h2(__float2half(v.x - __half2float(h0)),
                    __float2half(v.y - __half2float(h1)));
    lo2.y = pack_h2(__float2half(v.z - __half2float(h2)),
                    __float2half(v.w - __half2float(h3)));
    lo[i] = lo2;
}

// fused 4-way weight split: grid.y selects source; dst is [4][n4]
__global__ void split_h16_w4(const float4* __restrict__ s0,
                             const float4* __restrict__ s1,
                             const float4* __restrict__ s2,
                             const float4* __restrict__ s3,
                             uint2* __restrict__ dst, int n4) {
    int i = blockIdx.x * 256 + threadIdx.x;
    if (i >= n4) return;
    const float4* srcs[4] = {s0, s1, s2, s3};
    float4 v = srcs[blockIdx.y][i];
    uint2 ho;
    ho.x = pack_h2(__float2half(v.x), __float2half(v.y));
    ho.y = pack_h2(__float2half(v.z), __float2half(v.w));
    dst[(size_t)blockIdx.y * n4 + i] = ho;
}

// ============================================================================
// fp16 WMMA GEMM: C = (Ahi [+ Alo]) * B^T + bias
//   ATERMS: 1 or 2 A-operand terms.
//   MODE 0: C fp32 [M][N]
//   MODE 1: C fp16 single-rounded, head layout [N/128][M][128]
//   QKFUSED: grid.z selects between two (B, bias, Ch) sets.
// ============================================================================
#define FTILE_ELEMS (128 * FSLD)
#define FTILE_BYTES (FTILE_ELEMS * 2)          // 18432
#define F16_GEMM_SMEM_MAX (2 * 3 * FTILE_BYTES) // 110592

template <int ATERMS, int MODE, int QKFUSED>
__global__ __launch_bounds__(256, 1) void gemm_f16(
    const __half* __restrict__ Ahi, const __half* __restrict__ Alo,
    const __half* __restrict__ B0, const __half* __restrict__ B1,
    const float* __restrict__ bias0, const float* __restrict__ bias1,
    float* __restrict__ C,
    __half* __restrict__ Ch0, __half* __restrict__ Ch1,
    int M, int N)
{
    constexpr int TILES = ATERMS + 1;
    constexpr int BUFB  = TILES * FTILE_BYTES;

    extern __shared__ char smemg[];
    __half* sbuf = (__half*)smemg;
    const uint32_t sb = smem_u32(smemg);

    const __half* B    = (QKFUSED && blockIdx.z) ? B1 : B0;
    const float*  bias = (QKFUSED && blockIdx.z) ? bias1 : bias0;
    __half*       Ch   = (QKFUSED && blockIdx.z) ? Ch1 : Ch0;

    const int tid  = threadIdx.x;
    const int wid  = tid >> 5;
    const int m0   = blockIdx.y * BM;
    const int n0   = blockIdx.x * BN;
    const int wm   = (wid & 3) * 32;
    const int wn   = (wid >> 2) * 64;

    const __half* srcs[TILES];
    srcs[0] = Ahi + (size_t)m0 * GK;
    if (ATERMS == 2) srcs[1] = Alo + (size_t)m0 * GK;
    srcs[TILES - 1] = B + (size_t)n0 * GK;

    const int lrow0 = tid >> 3;
    const int lc16  = (tid & 7) * 8;

    auto load_chunk = [&](int kt, int buf) {
        const int kc = kt * BKC;
        #pragma unroll
        for (int p = 0; p < TILES; p++) {
            const __half* gsrc = srcs[p] + (size_t)lrow0 * GK + kc + lc16;
            uint32_t dst = sb + buf * BUFB + p * FTILE_BYTES
                         + (lrow0 * FSLD + lc16) * 2;
            #pragma unroll
            for (int i = 0; i < 4; i++)
                CP_ASYNC16(dst + i * (32 * FSLD * 2), gsrc + (size_t)(i * 32) * GK);
        }
    };

    wmma::fragment<wmma::accumulator, 16, 16, 16, float> acc[2][4];
    #pragma unroll
    for (int t = 0; t < 2; t++)
        #pragma unroll
        for (int u = 0; u < 4; u++) wmma::fill_fragment(acc[t][u], 0.0f);

    load_chunk(0, 0);
    CP_ASYNC_COMMIT();
    CP_ASYNC_WAIT0();
    __syncthreads();

    for (int kt = 0; kt < NKC; kt++) {
        const int cur = kt & 1;
        if (kt + 1 < NKC) {
            load_chunk(kt + 1, cur ^ 1);
            CP_ASYNC_COMMIT();
        }

        const __half* base = sbuf + cur * (BUFB / 2);
        const __half* pAhi = base;
        const __half* pAlo = base + FTILE_ELEMS;          // valid iff ATERMS==2
        const __half* pB   = base + (TILES - 1) * FTILE_ELEMS;

        #pragma unroll
        for (int ks = 0; ks < 4; ks++) {
            wmma::fragment<wmma::matrix_a, 16, 16, 16, __half, wmma::row_major> ah[2], al[2];
            wmma::fragment<wmma::matrix_b, 16, 16, 16, __half, wmma::col_major> bh[4];
            #pragma unroll
            for (int t = 0; t < 2; t++) {
                wmma::load_matrix_sync(ah[t], pAhi + (wm + t * 16) * FSLD + ks * 16, FSLD);
                if (ATERMS == 2)
                    wmma::load_matrix_sync(al[t], pAlo + (wm + t * 16) * FSLD + ks * 16, FSLD);
            }
            #pragma unroll
            for (int u = 0; u < 4; u++)
                wmma::load_matrix_sync(bh[u], pB + (wn + u * 16) * FSLD + ks * 16, FSLD);
            #pragma unroll
            for (int t = 0; t < 2; t++)
                #pragma unroll
                for (int u = 0; u < 4; u++) {
                    wmma::mma_sync(acc[t][u], ah[t], bh[u], acc[t][u]);
                    if (ATERMS == 2)
                        wmma::mma_sync(acc[t][u], al[t], bh[u], acc[t][u]);
                }
        }

        if (kt + 1 < NKC) CP_ASYNC_WAIT0();
        __syncthreads();
    }

    float* sC = (float*)smemg;
    const int CLD = 132;
    #pragma unroll
    for (int t = 0; t < 2; t++)
        #pragma unroll
        for (int u = 0; u < 4; u++)
            wmma::store_matrix_sync(sC + (wm + t * 16) * CLD + wn + u * 16,
                                    acc[t][u], CLD, wmma::mem_row_major);
    __syncthreads();

    #pragma unroll
    for (int i = 0; i < 16; i++) {
        const int flat4 = tid + i * 256;
        const int row = flat4 >> 5;
        const int c   = (flat4 & 31) * 4;
        float v0 = sC[row * CLD + c + 0] + bias[n0 + c + 0];
        float v1 = sC[row * CLD + c + 1] + bias[n0 + c + 1];
        float v2 = sC[row * CLD + c + 2] + bias[n0 + c + 2];
        float v3 = sC[row * CLD + c + 3] + bias[n0 + c + 3];
        if (MODE == 0) {
            *(float4*)(C + (size_t)(m0 + row) * N + n0 + c) =
                make_float4(v0, v1, v2, v3);
        } else {
            size_t idx = (size_t)blockIdx.x * (size_t)M * 128 + (size_t)(m0 + row) * 128 + c;
            uint2 ho;
            ho.x = pack_h2(__float2half(v0), __float2half(v1));
            ho.y = pack_h2(__float2half(v2), __float2half(v3));
            *(uint2*)(Ch + idx) = ho;
        }
    }
}

// ============================================================================
// fp16 WMMA flash attention (causal): single-term S and PV, per-tile max,
// online corr on fp32 fragment accumulators, single-rounded fp16 output.
//   CTA: 128 queries x 1 head; 64-key tiles; 8 warps.
// ============================================================================
#define AQ_OFF  0
#define AKV_OFF 34816
#define KVBUF   17408
#define AS_OFF  69632
#define AP_OFF  104448
#define ASL_OFF 122880
#define ASW_OFF 123392
#define ATTN_SMEM 123424
#define QKSCALE 0.08838834764831843f   // 1/sqrt(128)

__global__ __launch_bounds__(256, 1) void flash_attn_f16(
    const __half* __restrict__ Q16, const __half* __restrict__ K16,
    const __half* __restrict__ V16,
    __half* __restrict__ O16)
{
    extern __shared__ char smem[];
    const uint32_t sb = smem_u32(smem);

    __half* sQ  = (__half*)(smem + AQ_OFF);
    float*  sS  = (float*)(smem + AS_OFF);
    __half* sP  = (__half*)(smem + AP_OFF);
    float*  sl  = (float*)(smem + ASL_OFF);
    float*  swm = (float*)(smem + ASW_OFF);

    const int tid = threadIdx.x;
    const int wid = tid >> 5;
    const int lane = tid & 31;
    const int qt  = gridDim.x - 1 - blockIdx.x;   // heavy CTAs first
    const int h   = blockIdx.y;
    const int ntiles = 2 * (qt + 1);

    const __half* Qh = Q16 + ((size_t)h * S_LEN + (size_t)qt * 128) * HD;
    const __half* Kh = K16 + (size_t)h * S_LEN * HD;
    const __half* Vh = V16 + (size_t)h * S_LEN * HD;

    auto loadQ = [&]() {
        #pragma unroll
        for (int rep = 0; rep < 8; rep++) {
            int id  = tid + rep * 256;            // 0..2047
            int row = id >> 4, cc = (id & 15) * 8;
            CP_ASYNC16(sb + AQ_OFF + (row * 136 + cc) * 2, Qh + (size_t)row * HD + cc);
        }
    };
    auto loadKV = [&](const __half* Tp, int ktile, int buf) {
        const size_t base = (size_t)ktile * 64 * HD;
        #pragma unroll
        for (int rep = 0; rep < 4; rep++) {
            int id  = tid + rep * 256;            // 0..1023
            int row = id >> 4, cc = (id & 15) * 8;
            CP_ASYNC16(sb + AKV_OFF + buf * KVBUF + (row * 136 + cc) * 2,
                       Tp + base + (size_t)row * HD + cc);
        }
    };

    loadQ();
    loadKV(Kh, 0, 0);
    CP_ASYNC_COMMIT();

    wmma::fragment<wmma::accumulator, 16, 16, 16, float> facc[2][4];
    #pragma unroll
    for (int t = 0; t < 2; t++)
        #pragma unroll
        for (int u = 0; u < 4; u++) wmma::fill_fragment(facc[t][u], 0.0f);
    float lrun = 0.0f;
    float Mrun = -1.0e30f;

    const int wm  = (wid & 3) * 32;       // warp q-rows
    const int wsn = (wid >> 2) * 32;      // warp key-cols (S phase)
    const int wn  = (wid >> 2) * 64;      // warp d-cols (PV phase)

    for (int kt = 0; kt < ntiles; kt++) {
        const int cur = kt & 1;
        __half* kvS = (__half*)(smem + AKV_OFF + cur * KVBUF);

        CP_ASYNC_WAIT0();
        __syncthreads();

        // ---- S = Q K^T (single term) ----
        {
            wmma::fragment<wmma::accumulator, 16, 16, 16, float> accs[2][2];
            #pragma unroll
            for (int t = 0; t < 2; t++)
                #pragma unroll
                for (int u = 0; u < 2; u++) wmma::fill_fragment(accs[t][u], 0.0f);

            #pragma unroll
            for (int ks = 0; ks < 8; ks++) {
                wmma::fragment<wmma::matrix_a, 16, 16, 16, __half, wmma::row_major> ah[2];
                wmma::fragment<wmma::matrix_b, 16, 16, 16, __half, wmma::col_major> bh[2];
                #pragma unroll
                for (int t = 0; t < 2; t++)
                    wmma::load_matrix_sync(ah[t], sQ + (wm + t * 16) * 136 + ks * 16, 136);
                #pragma unroll
                for (int u = 0; u < 2; u++)
                    wmma::load_matrix_sync(bh[u], kvS + (wsn + u * 16) * 136 + ks * 16, 136);
                #pragma unroll
                for (int t = 0; t < 2; t++)
                    #pragma unroll
                    for (int u = 0; u < 2; u++)
                        wmma::mma_sync(accs[t][u], ah[t], bh[u], accs[t][u]);
            }
            #pragma unroll
            for (int t = 0; t < 2; t++)
                #pragma unroll
                for (int u = 0; u < 2; u++)
                    wmma::store_matrix_sync(sS + (wm + t * 16) * 68 + wsn + u * 16,
                                            accs[t][u], 68, wmma::mem_row_major);
        }
        __syncthreads();

        // ---- prefetch: V(kt) overwrites K(kt) in buf cur; K(kt+1) -> other buf
        loadKV(Vh, kt, cur);
        CP_ASYNC_COMMIT();
        if (kt + 1 < ntiles) loadKV(Kh, kt + 1, cur ^ 1);
        CP_ASYNC_COMMIT();

        // ---- tile max (CTA-wide, on raw logits) ----
        {
            const float* Srow = sS + (tid >> 1) * 68 + (tid & 1) * 32;
            float lm = -1.0e30f;
            #pragma unroll
            for (int j = 0; j < 32; j++) lm = fmaxf(lm, Srow[j]);
            #pragma unroll
            for (int o = 16; o > 0; o >>= 1)
                lm = fmaxf(lm, __shfl_xor_sync(0xffffffffu, lm, o));
            if (lane == 0) swm[wid] = lm;
        }
        __syncthreads();
        float mfs = swm[0];
        #pragma unroll
        for (int w = 1; w < 8; w++) mfs = fmaxf(mfs, swm[w]);
        const float m_sc = mfs * QKSCALE;
        const float Mnew = fmaxf(Mrun, m_sc);
        const float corr = __expf(Mrun - Mnew);
        Mrun = Mnew;

        // ---- softmax: p = exp(s*scale - Mnew), mask, fp16 store ----
        {
            const int row = tid >> 1;
            const int c0  = (tid & 1) * 32;
            const int qglob = qt * 128 + row;
            const int kbase = kt * 64 + c0;
            const bool needMask = (kt >= 2 * qt);
            const float* Srow = sS + row * 68 + c0;
            __half* Pr = sP + row * 72 + c0;
            float psum = 0.0f;
            #pragma unroll
            for (int j = 0; j < 32; j += 2) {
                float p0 = __expf(Srow[j]     * QKSCALE - Mnew);
                float p1 = __expf(Srow[j + 1] * QKSCALE - Mnew);
                if (needMask) {
                    if (kbase + j     > qglob) p0 = 0.0f;
                    if (kbase + j + 1 > qglob) p1 = 0.0f;
                }
                psum += p0 + p1;
                *(uint32_t*)(Pr + j) = pack_h2(__float2half(p0), __float2half(p1));
            }
            psum += __shfl_xor_sync(0xffffffffu, psum, 1);
            lrun = lrun * corr + psum;
        }

        // ---- rescale persistent accumulators by corr (skip when corr==1) ----
        if (corr != 1.0f) {
            #pragma unroll
            for (int t = 0; t < 2; t++)
                #pragma unroll
                for (int u = 0; u < 4; u++)
                    #pragma unroll
                    for (int e = 0; e < facc[t][u].num_elements; e++)
                        facc[t][u].x[e] *= corr;
        }

        CP_ASYNC_WAIT1();          // V ready (K may still be in flight)
        __syncthreads();           // P visible to all warps

        // ---- O += P V (single term, direct fp32 accumulation) ----
        #pragma unroll
        for (int ks = 0; ks < 4; ks++) {
            wmma::fragment<wmma::matrix_a, 16, 16, 16, __half, wmma::row_major> pa[2];
            wmma::fragment<wmma::matrix_b, 16, 16, 16, __half, wmma::row_major> vb[4];
            #pragma unroll
            for (int t = 0; t < 2; t++)
                wmma::load_matrix_sync(pa[t], sP + (wm + t * 16) * 72 + ks * 16, 72);
            #pragma unroll
            for (int u = 0; u < 4; u++)
                wmma::load_matrix_sync(vb[u], kvS + (ks * 16) * 136 + wn + u * 16, 136);
            #pragma unroll
            for (int t = 0; t < 2; t++)
                #pragma unroll
                for (int u = 0; u < 4; u++)
                    wmma::mma_sync(facc[t][u], pa[t], vb[u], facc[t][u]);
        }
    }

    CP_ASYNC_WAIT0();
    __syncthreads();

    // ---- epilogue: O = facc / lrun, single-rounded fp16, write [s][DIM] ----
    float* sO = (float*)(smem + AKV_OFF);     // [128][132] fp32
    const int OLD = 132;
    #pragma unroll
    for (int t = 0; t < 2; t++)
        #pragma unroll
        for (int u = 0; u < 4; u++)
            wmma::store_matrix_sync(sO + (wm + t * 16) * OLD + wn + u * 16,
                                    facc[t][u], OLD, wmma::mem_row_major);
    if ((tid & 1) == 0) sl[tid >> 1] = lrun;
    __syncthreads();

    {
        const int row = tid >> 1;
        const int c0  = (tid & 1) * 64;
        const float inv = 1.0f / sl[row];
        const size_t dbase = (size_t)(qt * 128 + row) * DIM + (size_t)h * HD + c0;
        #pragma unroll
        for (int j = 0; j < 64; j += 2) {
            float o0 = sO[row * OLD + c0 + j]     * inv;
            float o1 = sO[row * OLD + c0 + j + 1] * inv;
            *(uint32_t*)(O16 + dbase + j) =
                pack_h2(__float2half(o0), __float2half(o1));
        }
    }
}

// ============================================================================
// launch
// ============================================================================
extern "C" void kernel_launch(void* const* d_in, const int* in_sizes, int n_in,
                              void* d_out, int out_size)
{
    const float* X  = (const float*)d_in[0];
    const float* Wq = (const float*)d_in[1];
    const float* bq = (const float*)d_in[2];
    const float* Wk = (const float*)d_in[3];
    const float* bk = (const float*)d_in[4];
    const float* Wv = (const float*)d_in[5];
    const float* bv = (const float*)d_in[6];
    const float* Wo = (const float*)d_in[7];
    const float* bo = (const float*)d_in[8];

    __half *Q16, *K16, *V16, *O16, *Xhi, *Xlo, *W16;
    cudaGetSymbolAddress((void**)&Q16, g_Q16);
    cudaGetSymbolAddress((void**)&K16, g_K16);
    cudaGetSymbolAddress((void**)&V16, g_V16);
    cudaGetSymbolAddress((void**)&O16, g_O16);
    cudaGetSymbolAddress((void**)&Xhi, g_Xhi);
    cudaGetSymbolAddress((void**)&Xlo, g_Xlo);
    cudaGetSymbolAddress((void**)&W16, g_W16);

    const int NX4 = S_LEN * DIM / 4;
    const int NW4 = DIM * DIM / 4;

    split_hi_lo<<<(NX4 + 255) / 256, 256>>>((const float4*)X,
        (uint2*)Xhi, (uint2*)Xlo, NX4);
    dim3 gW((NW4 + 255) / 256, 4);
    split_h16_w4<<<gW, 256>>>((const float4*)Wq, (const float4*)Wk,
                              (const float4*)Wv, (const float4*)Wo,
                              (uint2*)W16, NW4);

    cudaFuncSetAttribute(gemm_f16<1, 1, 1>,
        cudaFuncAttributeMaxDynamicSharedMemorySize, F16_GEMM_SMEM_MAX);
    cudaFuncSetAttribute(gemm_f16<2, 1, 0>,
        cudaFuncAttributeMaxDynamicSharedMemorySize, F16_GEMM_SMEM_MAX);
    cudaFuncSetAttribute(gemm_f16<1, 0, 0>,
        cudaFuncAttributeMaxDynamicSharedMemorySize, F16_GEMM_SMEM_MAX);
    cudaFuncSetAttribute(flash_attn_f16,
        cudaFuncAttributeMaxDynamicSharedMemorySize, ATTN_SMEM);

    const int smem1 = 2 * 2 * FTILE_BYTES;    // ATERMS=1
    const int smem2 = 2 * 3 * FTILE_BYTES;    // ATERMS=2

    // Q + K projections fused: 1-term (logit path, error attenuated)
    dim3 gQK(DIM / BN, S_LEN / BM, 2);
    gemm_f16<1, 1, 1><<<gQK, 256, smem1>>>(Xhi, nullptr,
        W16 + 0 * (size_t)DIM * DIM, W16 + 1 * (size_t)DIM * DIM,
        bq, bk, nullptr, Q16, K16, S_LEN, DIM);

    // V projection: 2-term (direct path)
    dim3 gGemm(DIM / BN, S_LEN / BM);
    gemm_f16<2, 1, 0><<<gGemm, 256, smem2>>>(Xhi, Xlo,
        W16 + 2 * (size_t)DIM * DIM, nullptr,
        bv, nullptr, nullptr, V16, nullptr, S_LEN, DIM);

    dim3 gAttn(S_LEN / 128, HEADS);
    flash_attn_f16<<<gAttn, 256, ATTN_SMEM>>>(Q16, K16, V16, O16);

    // O projection: 1-term (O single-rounded; error adds in quadrature)
    gemm_f16<1, 0, 0><<<gGemm, 256, smem1>>>(O16, nullptr,
        W16 + 3 * (size_t)DIM * DIM, nullptr,
        bo, nullptr, (float*)d_out, nullptr, nullptr, S_LEN, DIM);
}

// round 12
// speedup vs baseline: 9.5573x; 1.1176x over previous
#include <cuda_runtime.h>
#include <cuda_fp16.h>
#include <mma.h>
#include <math_constants.h>
#include <cstdint>

using namespace nvcuda;

#define S_LEN 4096
#define DIM   2048
#define HEADS 16
#define HD    128
#define GK    2048
#define BM    128
#define BN    128
#define BKC   64
#define NKC   (GK / BKC)    // 32
#define FSLD  72            // gemm smem row stride (fp16)

// ---------------- scratch (allocation-free rule: __device__ globals) ----------
__device__ __half g_Q16[HEADS * S_LEN * HD];
__device__ __half g_K16[HEADS * S_LEN * HD];
__device__ __half g_V16[HEADS * S_LEN * HD];
__device__ __half g_O16[S_LEN * DIM];
__device__ __half g_Xhi[S_LEN * DIM];
__device__ __half g_Xlo[S_LEN * DIM];
__device__ __half g_W16[4][DIM * DIM];

// ---------------- helpers ------------------------------------------------------
__device__ __forceinline__ uint32_t smem_u32(const void* p) {
    uint32_t a;
    asm("{ .reg .u64 t; cvta.to.shared.u64 t, %1; cvt.u32.u64 %0, t; }"
        : "=r"(a) : "l"(p));
    return a;
}
#define CP_ASYNC16(dst_u32, src_ptr) \
    asm volatile("cp.async.cg.shared.global [%0], [%1], 16;" \
        :: "r"(dst_u32), "l"(src_ptr) : "memory")
#define CP_ASYNC_COMMIT() asm volatile("cp.async.commit_group;" ::: "memory")
#define CP_ASYNC_WAIT0()  asm volatile("cp.async.wait_group 0;" ::: "memory")
#define CP_ASYNC_WAIT1()  asm volatile("cp.async.wait_group 1;" ::: "memory")

__device__ __forceinline__ uint32_t pack_h2(__half a, __half b) {
    __half2 t = __halves2half2(a, b);
    return *(uint32_t*)&t;
}

// ============================================================================
// splits
// ============================================================================
__global__ void split_hi_lo(const float4* __restrict__ src,
                            uint2* __restrict__ hi, uint2* __restrict__ lo,
                            int n4) {
    int i = blockIdx.x * 256 + threadIdx.x;
    if (i >= n4) return;
    float4 v = src[i];
    __half h0 = __float2half(v.x), h1 = __float2half(v.y);
    __half h2 = __float2half(v.z), h3 = __float2half(v.w);
    uint2 ho;
    ho.x = pack_h2(h0, h1);  ho.y = pack_h2(h2, h3);
    hi[i] = ho;
    uint2 lo2;
    lo2.x = pack_h2(__float2half(v.x - __half2float(h0)),
                    __float2half(v.y - __half2float(h1)));
    lo2.y = pack_h2(__float2half(v.z - __half2float(h2)),
                    __float2half(v.w - __half2float(h3)));
    lo[i] = lo2;
}

__global__ void split_h16_w4(const float4* __restrict__ s0,
                             const float4* __restrict__ s1,
                             const float4* __restrict__ s2,
                             const float4* __restrict__ s3,
                             uint2* __restrict__ dst, int n4) {
    int i = blockIdx.x * 256 + threadIdx.x;
    if (i >= n4) return;
    const float4* srcs[4] = {s0, s1, s2, s3};
    float4 v = srcs[blockIdx.y][i];
    uint2 ho;
    ho.x = pack_h2(__float2half(v.x), __float2half(v.y));
    ho.y = pack_h2(__float2half(v.z), __float2half(v.w));
    dst[(size_t)blockIdx.y * n4 + i] = ho;
}

// ============================================================================
// fp16 WMMA GEMM: C = (Ahi [+ Alo]) * B^T + bias   — now 2 CTAs/SM
// ============================================================================
#define FTILE_ELEMS (128 * FSLD)
#define FTILE_BYTES (FTILE_ELEMS * 2)          // 18432
#define F16_GEMM_SMEM_MAX (2 * 3 * FTILE_BYTES) // 110592

template <int ATERMS, int MODE, int QKFUSED>
__global__ __launch_bounds__(256, 2) void gemm_f16(
    const __half* __restrict__ Ahi, const __half* __restrict__ Alo,
    const __half* __restrict__ B0, const __half* __restrict__ B1,
    const float* __restrict__ bias0, const float* __restrict__ bias1,
    float* __restrict__ C,
    __half* __restrict__ Ch0, __half* __restrict__ Ch1,
    int M, int N)
{
    constexpr int TILES = ATERMS + 1;
    constexpr int BUFB  = TILES * FTILE_BYTES;

    extern __shared__ char smemg[];
    __half* sbuf = (__half*)smemg;
    const uint32_t sb = smem_u32(smemg);

    const __half* B    = (QKFUSED && blockIdx.z) ? B1 : B0;
    const float*  bias = (QKFUSED && blockIdx.z) ? bias1 : bias0;
    __half*       Ch   = (QKFUSED && blockIdx.z) ? Ch1 : Ch0;

    const int tid  = threadIdx.x;
    const int wid  = tid >> 5;
    const int m0   = blockIdx.y * BM;
    const int n0   = blockIdx.x * BN;
    const int wm   = (wid & 3) * 32;
    const int wn   = (wid >> 2) * 64;

    const __half* srcs[TILES];
    srcs[0] = Ahi + (size_t)m0 * GK;
    if (ATERMS == 2) srcs[1] = Alo + (size_t)m0 * GK;
    srcs[TILES - 1] = B + (size_t)n0 * GK;

    const int lrow0 = tid >> 3;
    const int lc16  = (tid & 7) * 8;

    auto load_chunk = [&](int kt, int buf) {
        const int kc = kt * BKC;
        #pragma unroll
        for (int p = 0; p < TILES; p++) {
            const __half* gsrc = srcs[p] + (size_t)lrow0 * GK + kc + lc16;
            uint32_t dst = sb + buf * BUFB + p * FTILE_BYTES
                         + (lrow0 * FSLD + lc16) * 2;
            #pragma unroll
            for (int i = 0; i < 4; i++)
                CP_ASYNC16(dst + i * (32 * FSLD * 2), gsrc + (size_t)(i * 32) * GK);
        }
    };

    wmma::fragment<wmma::accumulator, 16, 16, 16, float> acc[2][4];
    #pragma unroll
    for (int t = 0; t < 2; t++)
        #pragma unroll
        for (int u = 0; u < 4; u++) wmma::fill_fragment(acc[t][u], 0.0f);

    load_chunk(0, 0);
    CP_ASYNC_COMMIT();
    CP_ASYNC_WAIT0();
    __syncthreads();

    for (int kt = 0; kt < NKC; kt++) {
        const int cur = kt & 1;
        if (kt + 1 < NKC) {
            load_chunk(kt + 1, cur ^ 1);
            CP_ASYNC_COMMIT();
        }

        const __half* base = sbuf + cur * (BUFB / 2);
        const __half* pAhi = base;
        const __half* pAlo = base + FTILE_ELEMS;
        const __half* pB   = base + (TILES - 1) * FTILE_ELEMS;

        #pragma unroll
        for (int ks = 0; ks < 4; ks++) {
            wmma::fragment<wmma::matrix_a, 16, 16, 16, __half, wmma::row_major> ah[2], al[2];
            wmma::fragment<wmma::matrix_b, 16, 16, 16, __half, wmma::col_major> bh[4];
            #pragma unroll
            for (int t = 0; t < 2; t++) {
                wmma::load_matrix_sync(ah[t], pAhi + (wm + t * 16) * FSLD + ks * 16, FSLD);
                if (ATERMS == 2)
                    wmma::load_matrix_sync(al[t], pAlo + (wm + t * 16) * FSLD + ks * 16, FSLD);
            }
            #pragma unroll
            for (int u = 0; u < 4; u++)
                wmma::load_matrix_sync(bh[u], pB + (wn + u * 16) * FSLD + ks * 16, FSLD);
            #pragma unroll
            for (int t = 0; t < 2; t++)
                #pragma unroll
                for (int u = 0; u < 4; u++) {
                    wmma::mma_sync(acc[t][u], ah[t], bh[u], acc[t][u]);
                    if (ATERMS == 2)
                        wmma::mma_sync(acc[t][u], al[t], bh[u], acc[t][u]);
                }
        }

        if (kt + 1 < NKC) CP_ASYNC_WAIT0();
        __syncthreads();
    }

    float* sC = (float*)smemg;
    const int CLD = 132;
    #pragma unroll
    for (int t = 0; t < 2; t++)
        #pragma unroll
        for (int u = 0; u < 4; u++)
            wmma::store_matrix_sync(sC + (wm + t * 16) * CLD + wn + u * 16,
                                    acc[t][u], CLD, wmma::mem_row_major);
    __syncthreads();

    #pragma unroll
    for (int i = 0; i < 16; i++) {
        const int flat4 = tid + i * 256;
        const int row = flat4 >> 5;
        const int c   = (flat4 & 31) * 4;
        float v0 = sC[row * CLD + c + 0] + bias[n0 + c + 0];
        float v1 = sC[row * CLD + c + 1] + bias[n0 + c + 1];
        float v2 = sC[row * CLD + c + 2] + bias[n0 + c + 2];
        float v3 = sC[row * CLD + c + 3] + bias[n0 + c + 3];
        if (MODE == 0) {
            *(float4*)(C + (size_t)(m0 + row) * N + n0 + c) =
                make_float4(v0, v1, v2, v3);
        } else {
            size_t idx = (size_t)blockIdx.x * (size_t)M * 128 + (size_t)(m0 + row) * 128 + c;
            uint2 ho;
            ho.x = pack_h2(__float2half(v0), __float2half(v1));
            ho.y = pack_h2(__float2half(v2), __float2half(v3));
            *(uint2*)(Ch + idx) = ho;
        }
    }
}

// ============================================================================
// fp16 WMMA flash attention (causal) — 2 CTAs/SM.
// SMEM (bytes):
//   Q  fp16 [128][136] @0          (34816)
//   KV bufs [64][136]  @34816 + b*17408   (34816)
//   S  fp32 [128][68]  @69632      (34816)
//   P  fp16 ALIASED inside S rows: P[row] = bytes 128..271 of S row
//     (P base = S base + 64 halves, row stride 136 halves)
//   sl @104448 (512), swm @104960 (32)   -> total 104992
// Epilogue fp32 O [128][132] (67584) aliases @34816 (KV+S).
// ============================================================================
#define AQ_OFF  0
#define AKV_OFF 34816
#define KVBUF   17408
#define AS_OFF  69632
#define ASL_OFF 104448
#define ASW_OFF 104960
#define ATTN_SMEM 105024
#define QKSCALE 0.08838834764831843f   // 1/sqrt(128)

__global__ __launch_bounds__(256, 2) void flash_attn_f16(
    const __half* __restrict__ Q16, const __half* __restrict__ K16,
    const __half* __restrict__ V16,
    __half* __restrict__ O16)
{
    extern __shared__ char smem[];
    const uint32_t sb = smem_u32(smem);

    __half* sQ  = (__half*)(smem + AQ_OFF);
    float*  sS  = (float*)(smem + AS_OFF);
    __half* sP  = (__half*)(smem + AS_OFF) + 64;   // aliased: bytes 128.. of S rows
    float*  sl  = (float*)(smem + ASL_OFF);
    float*  swm = (float*)(smem + ASW_OFF);
    const int PLD = 136;                           // P row stride in halves (=272B)

    const int tid = threadIdx.x;
    const int wid = tid >> 5;
    const int lane = tid & 31;
    const int qt  = gridDim.x - 1 - blockIdx.x;   // heavy CTAs first
    const int h   = blockIdx.y;
    const int ntiles = 2 * (qt + 1);

    const __half* Qh = Q16 + ((size_t)h * S_LEN + (size_t)qt * 128) * HD;
    const __half* Kh = K16 + (size_t)h * S_LEN * HD;
    const __half* Vh = V16 + (size_t)h * S_LEN * HD;

    auto loadQ = [&]() {
        #pragma unroll
        for (int rep = 0; rep < 8; rep++) {
            int id  = tid + rep * 256;
            int row = id >> 4, cc = (id & 15) * 8;
            CP_ASYNC16(sb + AQ_OFF + (row * 136 + cc) * 2, Qh + (size_t)row * HD + cc);
        }
    };
    auto loadKV = [&](const __half* Tp, int ktile, int buf) {
        const size_t base = (size_t)ktile * 64 * HD;
        #pragma unroll
        for (int rep = 0; rep < 4; rep++) {
            int id  = tid + rep * 256;
            int row = id >> 4, cc = (id & 15) * 8;
            CP_ASYNC16(sb + AKV_OFF + buf * KVBUF + (row * 136 + cc) * 2,
                       Tp + base + (size_t)row * HD + cc);
        }
    };

    loadQ();
    loadKV(Kh, 0, 0);
    CP_ASYNC_COMMIT();

    wmma::fragment<wmma::accumulator, 16, 16, 16, float> facc[2][4];
    #pragma unroll
    for (int t = 0; t < 2; t++)
        #pragma unroll
        for (int u = 0; u < 4; u++) wmma::fill_fragment(facc[t][u], 0.0f);
    float lrun = 0.0f;
    float Mrun = -1.0e30f;

    const int wm  = (wid & 3) * 32;
    const int wsn = (wid >> 2) * 32;
    const int wn  = (wid >> 2) * 64;

    for (int kt = 0; kt < ntiles; kt++) {
        const int cur = kt & 1;
        __half* kvS = (__half*)(smem + AKV_OFF + cur * KVBUF);

        CP_ASYNC_WAIT0();
        __syncthreads();

        // ---- S = Q K^T ----
        {
            wmma::fragment<wmma::accumulator, 16, 16, 16, float> accs[2][2];
            #pragma unroll
            for (int t = 0; t < 2; t++)
                #pragma unroll
                for (int u = 0; u < 2; u++) wmma::fill_fragment(accs[t][u], 0.0f);

            #pragma unroll
            for (int ks = 0; ks < 8; ks++) {
                wmma::fragment<wmma::matrix_a, 16, 16, 16, __half, wmma::row_major> ah[2];
                wmma::fragment<wmma::matrix_b, 16, 16, 16, __half, wmma::col_major> bh[2];
                #pragma unroll
                for (int t = 0; t < 2; t++)
                    wmma::load_matrix_sync(ah[t], sQ + (wm + t * 16) * 136 + ks * 16, 136);
                #pragma unroll
                for (int u = 0; u < 2; u++)
                    wmma::load_matrix_sync(bh[u], kvS + (wsn + u * 16) * 136 + ks * 16, 136);
                #pragma unroll
                for (int t = 0; t < 2; t++)
                    #pragma unroll
                    for (int u = 0; u < 2; u++)
                        wmma::mma_sync(accs[t][u], ah[t], bh[u], accs[t][u]);
            }
            #pragma unroll
            for (int t = 0; t < 2; t++)
                #pragma unroll
                for (int u = 0; u < 2; u++)
                    wmma::store_matrix_sync(sS + (wm + t * 16) * 68 + wsn + u * 16,
                                            accs[t][u], 68, wmma::mem_row_major);
        }
        __syncthreads();

        // ---- prefetch ----
        loadKV(Vh, kt, cur);
        CP_ASYNC_COMMIT();
        if (kt + 1 < ntiles) loadKV(Kh, kt + 1, cur ^ 1);
        CP_ASYNC_COMMIT();

        // ---- tile max ----
        {
            const float* Srow = sS + (tid >> 1) * 68 + (tid & 1) * 32;
            float lm = -1.0e30f;
            #pragma unroll
            for (int j = 0; j < 32; j++) lm = fmaxf(lm, Srow[j]);
            #pragma unroll
            for (int o = 16; o > 0; o >>= 1)
                lm = fmaxf(lm, __shfl_xor_sync(0xffffffffu, lm, o));
            if (lane == 0) swm[wid] = lm;
        }
        __syncthreads();
        float mfs = swm[0];
        #pragma unroll
        for (int w = 1; w < 8; w++) mfs = fmaxf(mfs, swm[w]);
        const float m_sc = mfs * QKSCALE;
        const float Mnew = fmaxf(Mrun, m_sc);
        const float corr = __expf(Mrun - Mnew);
        Mrun = Mnew;

        // ---- softmax: read ALL of S row to regs, then write P (aliased) ----
        {
            const int row = tid >> 1;
            const int c0  = (tid & 1) * 32;
            const int qglob = qt * 128 + row;
            const int kbase = kt * 64 + c0;
            const bool needMask = (kt >= 2 * qt);
            const float* Srow = sS + row * 68 + c0;

            float sv[32];
            #pragma unroll
            for (int j = 0; j < 32; j++) sv[j] = Srow[j];   // reads BEFORE writes

            __half* Pr = sP + row * PLD + c0;
            float psum = 0.0f;
            #pragma unroll
            for (int j = 0; j < 32; j += 2) {
                float p0 = __expf(sv[j]     * QKSCALE - Mnew);
                float p1 = __expf(sv[j + 1] * QKSCALE - Mnew);
                if (needMask) {
                    if (kbase + j     > qglob) p0 = 0.0f;
                    if (kbase + j + 1 > qglob) p1 = 0.0f;
                }
                psum += p0 + p1;
                *(uint32_t*)(Pr + j) = pack_h2(__float2half(p0), __float2half(p1));
            }
            psum += __shfl_xor_sync(0xffffffffu, psum, 1);
            lrun = lrun * corr + psum;
        }

        // ---- rescale persistent accumulators (skip when corr==1) ----
        if (corr != 1.0f) {
            #pragma unroll
            for (int t = 0; t < 2; t++)
                #pragma unroll
                for (int u = 0; u < 4; u++)
                    #pragma unroll
                    for (int e = 0; e < facc[t][u].num_elements; e++)
                        facc[t][u].x[e] *= corr;
        }

        CP_ASYNC_WAIT1();
        __syncthreads();

        // ---- O += P V ----
        #pragma unroll
        for (int ks = 0; ks < 4; ks++) {
            wmma::fragment<wmma::matrix_a, 16, 16, 16, __half, wmma::row_major> pa[2];
            wmma::fragment<wmma::matrix_b, 16, 16, 16, __half, wmma::row_major> vb[4];
            #pragma unroll
            for (int t = 0; t < 2; t++)
                wmma::load_matrix_sync(pa[t], sP + (wm + t * 16) * PLD + ks * 16, PLD);
            #pragma unroll
            for (int u = 0; u < 4; u++)
                wmma::load_matrix_sync(vb[u], kvS + (ks * 16) * 136 + wn + u * 16, 136);
            #pragma unroll
            for (int t = 0; t < 2; t++)
                #pragma unroll
                for (int u = 0; u < 4; u++)
                    wmma::mma_sync(facc[t][u], pa[t], vb[u], facc[t][u]);
        }
    }

    CP_ASYNC_WAIT0();
    __syncthreads();

    // ---- epilogue: O = facc / lrun, fp16, write [s][DIM] ----
    float* sO = (float*)(smem + AKV_OFF);     // [128][132] fp32
    const int OLD = 132;
    #pragma unroll
    for (int t = 0; t < 2; t++)
        #pragma unroll
        for (int u = 0; u < 4; u++)
            wmma::store_matrix_sync(sO + (wm + t * 16) * OLD + wn + u * 16,
                                    facc[t][u], OLD, wmma::mem_row_major);
    if ((tid & 1) == 0) sl[tid >> 1] = lrun;
    __syncthreads();

    {
        const int row = tid >> 1;
        const int c0  = (tid & 1) * 64;
        const float inv = 1.0f / sl[row];
        const size_t dbase = (size_t)(qt * 128 + row) * DIM + (size_t)h * HD + c0;
        #pragma unroll
        for (int j = 0; j < 64; j += 2) {
            float o0 = sO[row * OLD + c0 + j]     * inv;
            float o1 = sO[row * OLD + c0 + j + 1] * inv;
            *(uint32_t*)(O16 + dbase + j) =
                pack_h2(__float2half(o0), __float2half(o1));
        }
    }
}

// ============================================================================
// launch
// ============================================================================
extern "C" void kernel_launch(void* const* d_in, const int* in_sizes, int n_in,
                              void* d_out, int out_size)
{
    const float* X  = (const float*)d_in[0];
    const float* Wq = (const float*)d_in[1];
    const float* bq = (const float*)d_in[2];
    const float* Wk = (const float*)d_in[3];
    const float* bk = (const float*)d_in[4];
    const float* Wv = (const float*)d_in[5];
    const float* bv = (const float*)d_in[6];
    const float* Wo = (const float*)d_in[7];
    const float* bo = (const float*)d_in[8];

    __half *Q16, *K16, *V16, *O16, *Xhi, *Xlo, *W16;
    cudaGetSymbolAddress((void**)&Q16, g_Q16);
    cudaGetSymbolAddress((void**)&K16, g_K16);
    cudaGetSymbolAddress((void**)&V16, g_V16);
    cudaGetSymbolAddress((void**)&O16, g_O16);
    cudaGetSymbolAddress((void**)&Xhi, g_Xhi);
    cudaGetSymbolAddress((void**)&Xlo, g_Xlo);
    cudaGetSymbolAddress((void**)&W16, g_W16);

    const int NX4 = S_LEN * DIM / 4;
    const int NW4 = DIM * DIM / 4;

    split_hi_lo<<<(NX4 + 255) / 256, 256>>>((const float4*)X,
        (uint2*)Xhi, (uint2*)Xlo, NX4);
    dim3 gW((NW4 + 255) / 256, 4);
    split_h16_w4<<<gW, 256>>>((const float4*)Wq, (const float4*)Wk,
                              (const float4*)Wv, (const float4*)Wo,
                              (uint2*)W16, NW4);

    cudaFuncSetAttribute(gemm_f16<1, 1, 1>,
        cudaFuncAttributeMaxDynamicSharedMemorySize, F16_GEMM_SMEM_MAX);
    cudaFuncSetAttribute(gemm_f16<2, 1, 0>,
        cudaFuncAttributeMaxDynamicSharedMemorySize, F16_GEMM_SMEM_MAX);
    cudaFuncSetAttribute(gemm_f16<1, 0, 0>,
        cudaFuncAttributeMaxDynamicSharedMemorySize, F16_GEMM_SMEM_MAX);
    cudaFuncSetAttribute(flash_attn_f16,
        cudaFuncAttributeMaxDynamicSharedMemorySize, ATTN_SMEM);

    const int smem1 = 2 * 2 * FTILE_BYTES;    // ATERMS=1  (73728)
    const int smem2 = 2 * 3 * FTILE_BYTES;    // ATERMS=2 (110592)

    // Q + K projections fused: 1-term
    dim3 gQK(DIM / BN, S_LEN / BM, 2);
    gemm_f16<1, 1, 1><<<gQK, 256, smem1>>>(Xhi, nullptr,
        W16 + 0 * (size_t)DIM * DIM, W16 + 1 * (size_t)DIM * DIM,
        bq, bk, nullptr, Q16, K16, S_LEN, DIM);

    // V projection: 2-term
    dim3 gGemm(DIM / BN, S_LEN / BM);
    gemm_f16<2, 1, 0><<<gGemm, 256, smem2>>>(Xhi, Xlo,
        W16 + 2 * (size_t)DIM * DIM, nullptr,
        bv, nullptr, nullptr, V16, nullptr, S_LEN, DIM);

    dim3 gAttn(S_LEN / 128, HEADS);
    flash_attn_f16<<<gAttn, 256, ATTN_SMEM>>>(Q16, K16, V16, O16);

    // O projection: 1-term
    gemm_f16<1, 0, 0><<<gGemm, 256, smem1>>>(O16, nullptr,
        W16 + 3 * (size_t)DIM * DIM, nullptr,
        bo, nullptr, (float*)d_out, nullptr, nullptr, S_LEN, DIM);
}

// round 13
// speedup vs baseline: 10.4591x; 1.0944x over previous
#include <cuda_runtime.h>
#include <cuda_fp16.h>
#include <mma.h>
#include <math_constants.h>
#include <cstdint>

using namespace nvcuda;

#define S_LEN 4096
#define DIM   2048
#define HEADS 16
#define HD    128
#define GK    2048
#define BM    128
#define BN    128
#define BKC   64
#define NKC   (GK / BKC)    // 32
#define FSLD  72            // gemm smem row stride (fp16)

// ---------------- scratch (allocation-free rule: __device__ globals) ----------
__device__ __half g_Q16[HEADS * S_LEN * HD];
__device__ __half g_K16[HEADS * S_LEN * HD];
__device__ __half g_V16[HEADS * S_LEN * HD];
__device__ __half g_O16[S_LEN * DIM];
__device__ __half g_X16[S_LEN * DIM];
__device__ __half g_W16[4][DIM * DIM];

// ---------------- helpers ------------------------------------------------------
__device__ __forceinline__ uint32_t smem_u32(const void* p) {
    uint32_t a;
    asm("{ .reg .u64 t; cvta.to.shared.u64 t, %1; cvt.u32.u64 %0, t; }"
        : "=r"(a) : "l"(p));
    return a;
}
#define CP_ASYNC16(dst_u32, src_ptr) \
    asm volatile("cp.async.cg.shared.global [%0], [%1], 16;" \
        :: "r"(dst_u32), "l"(src_ptr) : "memory")
#define CP_ASYNC_COMMIT() asm volatile("cp.async.commit_group;" ::: "memory")
#define CP_ASYNC_WAIT0()  asm volatile("cp.async.wait_group 0;" ::: "memory")
#define CP_ASYNC_WAIT1()  asm volatile("cp.async.wait_group 1;" ::: "memory")

__device__ __forceinline__ uint32_t pack_h2(__half a, __half b) {
    __half2 t = __halves2half2(a, b);
    return *(uint32_t*)&t;
}

// ============================================================================
// splits (single-rounded fp16 only — no lo parts needed anymore)
// ============================================================================
__global__ void split_h16(const float4* __restrict__ src,
                          uint2* __restrict__ dst, int n4) {
    int i = blockIdx.x * 256 + threadIdx.x;
    if (i >= n4) return;
    float4 v = src[i];
    uint2 ho;
    ho.x = pack_h2(__float2half(v.x), __float2half(v.y));
    ho.y = pack_h2(__float2half(v.z), __float2half(v.w));
    dst[i] = ho;
}

__global__ void split_h16_w4(const float4* __restrict__ s0,
                             const float4* __restrict__ s1,
                             const float4* __restrict__ s2,
                             const float4* __restrict__ s3,
                             uint2* __restrict__ dst, int n4) {
    int i = blockIdx.x * 256 + threadIdx.x;
    if (i >= n4) return;
    const float4* srcs[4] = {s0, s1, s2, s3};
    float4 v = srcs[blockIdx.y][i];
    uint2 ho;
    ho.x = pack_h2(__float2half(v.x), __float2half(v.y));
    ho.y = pack_h2(__float2half(v.z), __float2half(v.w));
    dst[(size_t)blockIdx.y * n4 + i] = ho;
}

// ============================================================================
// fp16 WMMA GEMM (1-term): C = A * B^T + bias   — 2 CTAs/SM
//   MODE 0: C fp32 [M][N]
//   MODE 1: C fp16 single-rounded, head layout [N/128][M][128]
//   NFUSE:  grid.z selects among NFUSE (B, bias, Ch) sets.
// ============================================================================
#define FTILE_ELEMS (128 * FSLD)
#define FTILE_BYTES (FTILE_ELEMS * 2)          // 18432
#define GEMM_SMEM   (2 * 2 * FTILE_BYTES)      // 73728

template <int MODE, int NFUSE>
__global__ __launch_bounds__(256, 2) void gemm_f16(
    const __half* __restrict__ A,
    const __half* __restrict__ B0, const __half* __restrict__ B1,
    const __half* __restrict__ B2,
    const float* __restrict__ bias0, const float* __restrict__ bias1,
    const float* __restrict__ bias2,
    float* __restrict__ C,
    __half* __restrict__ Ch0, __half* __restrict__ Ch1,
    __half* __restrict__ Ch2,
    int M, int N)
{
    extern __shared__ char smemg[];
    __half* sbuf = (__half*)smemg;
    const uint32_t sb = smem_u32(smemg);

    const __half* B    = B0;
    const float*  bias = bias0;
    __half*       Ch   = Ch0;
    if (NFUSE > 1) {
        if (blockIdx.z == 1) { B = B1; bias = bias1; Ch = Ch1; }
        else if (blockIdx.z == 2) { B = B2; bias = bias2; Ch = Ch2; }
    }

    const int tid  = threadIdx.x;
    const int wid  = tid >> 5;
    const int m0   = blockIdx.y * BM;
    const int n0   = blockIdx.x * BN;
    const int wm   = (wid & 3) * 32;
    const int wn   = (wid >> 2) * 64;

    const __half* srcA = A + (size_t)m0 * GK;
    const __half* srcB = B + (size_t)n0 * GK;

    const int lrow0 = tid >> 3;
    const int lc16  = (tid & 7) * 8;

    auto load_chunk = [&](int kt, int buf) {
        const int kc = kt * BKC;
        const __half* ga = srcA + (size_t)lrow0 * GK + kc + lc16;
        const __half* gb = srcB + (size_t)lrow0 * GK + kc + lc16;
        uint32_t da = sb + buf * (2 * FTILE_BYTES) + (lrow0 * FSLD + lc16) * 2;
        uint32_t db = da + FTILE_BYTES;
        #pragma unroll
        for (int i = 0; i < 4; i++) {
            CP_ASYNC16(da + i * (32 * FSLD * 2), ga + (size_t)(i * 32) * GK);
            CP_ASYNC16(db + i * (32 * FSLD * 2), gb + (size_t)(i * 32) * GK);
        }
    };

    wmma::fragment<wmma::accumulator, 16, 16, 16, float> acc[2][4];
    #pragma unroll
    for (int t = 0; t < 2; t++)
        #pragma unroll
        for (int u = 0; u < 4; u++) wmma::fill_fragment(acc[t][u], 0.0f);

    load_chunk(0, 0);
    CP_ASYNC_COMMIT();
    CP_ASYNC_WAIT0();
    __syncthreads();

    for (int kt = 0; kt < NKC; kt++) {
        const int cur = kt & 1;
        if (kt + 1 < NKC) {
            load_chunk(kt + 1, cur ^ 1);
            CP_ASYNC_COMMIT();
        }

        const __half* pA = sbuf + cur * (2 * FTILE_ELEMS);
        const __half* pB = pA + FTILE_ELEMS;

        #pragma unroll
        for (int ks = 0; ks < 4; ks++) {
            wmma::fragment<wmma::matrix_a, 16, 16, 16, __half, wmma::row_major> ah[2];
            wmma::fragment<wmma::matrix_b, 16, 16, 16, __half, wmma::col_major> bh[4];
            #pragma unroll
            for (int t = 0; t < 2; t++)
                wmma::load_matrix_sync(ah[t], pA + (wm + t * 16) * FSLD + ks * 16, FSLD);
            #pragma unroll
            for (int u = 0; u < 4; u++)
                wmma::load_matrix_sync(bh[u], pB + (wn + u * 16) * FSLD + ks * 16, FSLD);
            #pragma unroll
            for (int t = 0; t < 2; t++)
                #pragma unroll
                for (int u = 0; u < 4; u++)
                    wmma::mma_sync(acc[t][u], ah[t], bh[u], acc[t][u]);
        }

        if (kt + 1 < NKC) CP_ASYNC_WAIT0();
        __syncthreads();
    }

    float* sC = (float*)smemg;
    const int CLD = 132;
    #pragma unroll
    for (int t = 0; t < 2; t++)
        #pragma unroll
        for (int u = 0; u < 4; u++)
            wmma::store_matrix_sync(sC + (wm + t * 16) * CLD + wn + u * 16,
                                    acc[t][u], CLD, wmma::mem_row_major);
    __syncthreads();

    #pragma unroll
    for (int i = 0; i < 16; i++) {
        const int flat4 = tid + i * 256;
        const int row = flat4 >> 5;
        const int c   = (flat4 & 31) * 4;
        float v0 = sC[row * CLD + c + 0] + bias[n0 + c + 0];
        float v1 = sC[row * CLD + c + 1] + bias[n0 + c + 1];
        float v2 = sC[row * CLD + c + 2] + bias[n0 + c + 2];
        float v3 = sC[row * CLD + c + 3] + bias[n0 + c + 3];
        if (MODE == 0) {
            *(float4*)(C + (size_t)(m0 + row) * N + n0 + c) =
                make_float4(v0, v1, v2, v3);
        } else {
            size_t idx = (size_t)blockIdx.x * (size_t)M * 128 + (size_t)(m0 + row) * 128 + c;
            uint2 ho;
            ho.x = pack_h2(__float2half(v0), __float2half(v1));
            ho.y = pack_h2(__float2half(v2), __float2half(v3));
            *(uint2*)(Ch + idx) = ho;
        }
    }
}

// ============================================================================
// fp16 WMMA flash attention (causal) — 2 CTAs/SM (unchanged from round 12).
// ============================================================================
#define AQ_OFF  0
#define AKV_OFF 34816
#define KVBUF   17408
#define AS_OFF  69632
#define ASL_OFF 104448
#define ASW_OFF 104960
#define ATTN_SMEM 105024
#define QKSCALE 0.08838834764831843f   // 1/sqrt(128)

__global__ __launch_bounds__(256, 2) void flash_attn_f16(
    const __half* __restrict__ Q16, const __half* __restrict__ K16,
    const __half* __restrict__ V16,
    __half* __restrict__ O16)
{
    extern __shared__ char smem[];
    const uint32_t sb = smem_u32(smem);

    __half* sQ  = (__half*)(smem + AQ_OFF);
    float*  sS  = (float*)(smem + AS_OFF);
    __half* sP  = (__half*)(smem + AS_OFF) + 64;   // aliased in S row padding
    float*  sl  = (float*)(smem + ASL_OFF);
    float*  swm = (float*)(smem + ASW_OFF);
    const int PLD = 136;

    const int tid = threadIdx.x;
    const int wid = tid >> 5;
    const int lane = tid & 31;
    const int qt  = gridDim.x - 1 - blockIdx.x;
    const int h   = blockIdx.y;
    const int ntiles = 2 * (qt + 1);

    const __half* Qh = Q16 + ((size_t)h * S_LEN + (size_t)qt * 128) * HD;
    const __half* Kh = K16 + (size_t)h * S_LEN * HD;
    const __half* Vh = V16 + (size_t)h * S_LEN * HD;

    auto loadQ = [&]() {
        #pragma unroll
        for (int rep = 0; rep < 8; rep++) {
            int id  = tid + rep * 256;
            int row = id >> 4, cc = (id & 15) * 8;
            CP_ASYNC16(sb + AQ_OFF + (row * 136 + cc) * 2, Qh + (size_t)row * HD + cc);
        }
    };
    auto loadKV = [&](const __half* Tp, int ktile, int buf) {
        const size_t base = (size_t)ktile * 64 * HD;
        #pragma unroll
        for (int rep = 0; rep < 4; rep++) {
            int id  = tid + rep * 256;
            int row = id >> 4, cc = (id & 15) * 8;
            CP_ASYNC16(sb + AKV_OFF + buf * KVBUF + (row * 136 + cc) * 2,
                       Tp + base + (size_t)row * HD + cc);
        }
    };

    loadQ();
    loadKV(Kh, 0, 0);
    CP_ASYNC_COMMIT();

    wmma::fragment<wmma::accumulator, 16, 16, 16, float> facc[2][4];
    #pragma unroll
    for (int t = 0; t < 2; t++)
        #pragma unroll
        for (int u = 0; u < 4; u++) wmma::fill_fragment(facc[t][u], 0.0f);
    float lrun = 0.0f;
    float Mrun = -1.0e30f;

    const int wm  = (wid & 3) * 32;
    const int wsn = (wid >> 2) * 32;
    const int wn  = (wid >> 2) * 64;

    for (int kt = 0; kt < ntiles; kt++) {
        const int cur = kt & 1;
        __half* kvS = (__half*)(smem + AKV_OFF + cur * KVBUF);

        CP_ASYNC_WAIT0();
        __syncthreads();

        // ---- S = Q K^T ----
        {
            wmma::fragment<wmma::accumulator, 16, 16, 16, float> accs[2][2];
            #pragma unroll
            for (int t = 0; t < 2; t++)
                #pragma unroll
                for (int u = 0; u < 2; u++) wmma::fill_fragment(accs[t][u], 0.0f);

            #pragma unroll
            for (int ks = 0; ks < 8; ks++) {
                wmma::fragment<wmma::matrix_a, 16, 16, 16, __half, wmma::row_major> ah[2];
                wmma::fragment<wmma::matrix_b, 16, 16, 16, __half, wmma::col_major> bh[2];
                #pragma unroll
                for (int t = 0; t < 2; t++)
                    wmma::load_matrix_sync(ah[t], sQ + (wm + t * 16) * 136 + ks * 16, 136);
                #pragma unroll
                for (int u = 0; u < 2; u++)
                    wmma::load_matrix_sync(bh[u], kvS + (wsn + u * 16) * 136 + ks * 16, 136);
                #pragma unroll
                for (int t = 0; t < 2; t++)
                    #pragma unroll
                    for (int u = 0; u < 2; u++)
                        wmma::mma_sync(accs[t][u], ah[t], bh[u], accs[t][u]);
            }
            #pragma unroll
            for (int t = 0; t < 2; t++)
                #pragma unroll
                for (int u = 0; u < 2; u++)
                    wmma::store_matrix_sync(sS + (wm + t * 16) * 68 + wsn + u * 16,
                                            accs[t][u], 68, wmma::mem_row_major);
        }
        __syncthreads();

        // ---- prefetch ----
        loadKV(Vh, kt, cur);
        CP_ASYNC_COMMIT();
        if (kt + 1 < ntiles) loadKV(Kh, kt + 1, cur ^ 1);
        CP_ASYNC_COMMIT();

        // ---- tile max ----
        {
            const float* Srow = sS + (tid >> 1) * 68 + (tid & 1) * 32;
            float lm = -1.0e30f;
            #pragma unroll
            for (int j = 0; j < 32; j++) lm = fmaxf(lm, Srow[j]);
            #pragma unroll
            for (int o = 16; o > 0; o >>= 1)
                lm = fmaxf(lm, __shfl_xor_sync(0xffffffffu, lm, o));
            if (lane == 0) swm[wid] = lm;
        }
        __syncthreads();
        float mfs = swm[0];
        #pragma unroll
        for (int w = 1; w < 8; w++) mfs = fmaxf(mfs, swm[w]);
        const float m_sc = mfs * QKSCALE;
        const float Mnew = fmaxf(Mrun, m_sc);
        const float corr = __expf(Mrun - Mnew);
        Mrun = Mnew;

        // ---- softmax (reads S row to regs first; P aliased in padding) ----
        {
            const int row = tid >> 1;
            const int c0  = (tid & 1) * 32;
            const int qglob = qt * 128 + row;
            const int kbase = kt * 64 + c0;
            const bool needMask = (kt >= 2 * qt);
            const float* Srow = sS + row * 68 + c0;

            float sv[32];
            #pragma unroll
            for (int j = 0; j < 32; j++) sv[j] = Srow[j];

            __half* Pr = sP + row * PLD + c0;
            float psum = 0.0f;
            #pragma unroll
            for (int j = 0; j < 32; j += 2) {
                float p0 = __expf(sv[j]     * QKSCALE - Mnew);
                float p1 = __expf(sv[j + 1] * QKSCALE - Mnew);
                if (needMask) {
                    if (kbase + j     > qglob) p0 = 0.0f;
                    if (kbase + j + 1 > qglob) p1 = 0.0f;
                }
                psum += p0 + p1;
                *(uint32_t*)(Pr + j) = pack_h2(__float2half(p0), __float2half(p1));
            }
            psum += __shfl_xor_sync(0xffffffffu, psum, 1);
            lrun = lrun * corr + psum;
        }

        if (corr != 1.0f) {
            #pragma unroll
            for (int t = 0; t < 2; t++)
                #pragma unroll
                for (int u = 0; u < 4; u++)
                    #pragma unroll
                    for (int e = 0; e < facc[t][u].num_elements; e++)
                        facc[t][u].x[e] *= corr;
        }

        CP_ASYNC_WAIT1();
        __syncthreads();

        // ---- O += P V ----
        #pragma unroll
        for (int ks = 0; ks < 4; ks++) {
            wmma::fragment<wmma::matrix_a, 16, 16, 16, __half, wmma::row_major> pa[2];
            wmma::fragment<wmma::matrix_b, 16, 16, 16, __half, wmma::row_major> vb[4];
            #pragma unroll
            for (int t = 0; t < 2; t++)
                wmma::load_matrix_sync(pa[t], sP + (wm + t * 16) * PLD + ks * 16, PLD);
            #pragma unroll
            for (int u = 0; u < 4; u++)
                wmma::load_matrix_sync(vb[u], kvS + (ks * 16) * 136 + wn + u * 16, 136);
            #pragma unroll
            for (int t = 0; t < 2; t++)
                #pragma unroll
                for (int u = 0; u < 4; u++)
                    wmma::mma_sync(facc[t][u], pa[t], vb[u], facc[t][u]);
        }
    }

    CP_ASYNC_WAIT0();
    __syncthreads();

    // ---- epilogue ----
    float* sO = (float*)(smem + AKV_OFF);
    const int OLD = 132;
    #pragma unroll
    for (int t = 0; t < 2; t++)
        #pragma unroll
        for (int u = 0; u < 4; u++)
            wmma::store_matrix_sync(sO + (wm + t * 16) * OLD + wn + u * 16,
                                    facc[t][u], OLD, wmma::mem_row_major);
    if ((tid & 1) == 0) sl[tid >> 1] = lrun;
    __syncthreads();

    {
        const int row = tid >> 1;
        const int c0  = (tid & 1) * 64;
        const float inv = 1.0f / sl[row];
        const size_t dbase = (size_t)(qt * 128 + row) * DIM + (size_t)h * HD + c0;
        #pragma unroll
        for (int j = 0; j < 64; j += 2) {
            float o0 = sO[row * OLD + c0 + j]     * inv;
            float o1 = sO[row * OLD + c0 + j + 1] * inv;
            *(uint32_t*)(O16 + dbase + j) =
                pack_h2(__float2half(o0), __float2half(o1));
        }
    }
}

// ============================================================================
// launch
// ============================================================================
extern "C" void kernel_launch(void* const* d_in, const int* in_sizes, int n_in,
                              void* d_out, int out_size)
{
    const float* X  = (const float*)d_in[0];
    const float* Wq = (const float*)d_in[1];
    const float* bq = (const float*)d_in[2];
    const float* Wk = (const float*)d_in[3];
    const float* bk = (const float*)d_in[4];
    const float* Wv = (const float*)d_in[5];
    const float* bv = (const float*)d_in[6];
    const float* Wo = (const float*)d_in[7];
    const float* bo = (const float*)d_in[8];

    __half *Q16, *K16, *V16, *O16, *X16, *W16;
    cudaGetSymbolAddress((void**)&Q16, g_Q16);
    cudaGetSymbolAddress((void**)&K16, g_K16);
    cudaGetSymbolAddress((void**)&V16, g_V16);
    cudaGetSymbolAddress((void**)&O16, g_O16);
    cudaGetSymbolAddress((void**)&X16, g_X16);
    cudaGetSymbolAddress((void**)&W16, g_W16);

    const int NX4 = S_LEN * DIM / 4;
    const int NW4 = DIM * DIM / 4;

    split_h16<<<(NX4 + 255) / 256, 256>>>((const float4*)X, (uint2*)X16, NX4);
    dim3 gW((NW4 + 255) / 256, 4);
    split_h16_w4<<<gW, 256>>>((const float4*)Wq, (const float4*)Wk,
                              (const float4*)Wv, (const float4*)Wo,
                              (uint2*)W16, NW4);

    cudaFuncSetAttribute(gemm_f16<1, 3>,
        cudaFuncAttributeMaxDynamicSharedMemorySize, GEMM_SMEM);
    cudaFuncSetAttribute(gemm_f16<0, 1>,
        cudaFuncAttributeMaxDynamicSharedMemorySize, GEMM_SMEM);
    cudaFuncSetAttribute(flash_attn_f16,
        cudaFuncAttributeMaxDynamicSharedMemorySize, ATTN_SMEM);

    // Q + K + V projections fused: 1-term each
    dim3 gQKV(DIM / BN, S_LEN / BM, 3);
    gemm_f16<1, 3><<<gQKV, 256, GEMM_SMEM>>>(X16,
        W16 + 0 * (size_t)DIM * DIM, W16 + 1 * (size_t)DIM * DIM,
        W16 + 2 * (size_t)DIM * DIM,
        bq, bk, bv, nullptr, Q16, K16, V16, S_LEN, DIM);

    dim3 gAttn(S_LEN / 128, HEADS);
    flash_attn_f16<<<gAttn, 256, ATTN_SMEM>>>(Q16, K16, V16, O16);

    // O projection: 1-term
    dim3 gGemm(DIM / BN, S_LEN / BM);
    gemm_f16<0, 1><<<gGemm, 256, GEMM_SMEM>>>(O16,
        W16 + 3 * (size_t)DIM * DIM, nullptr, nullptr,
        bo, nullptr, nullptr, (float*)d_out, nullptr, nullptr, nullptr,
        S_LEN, DIM);
}